// round 11
// baseline (speedup 1.0000x reference)
#include <cuda_runtime.h>
#include <cuda_bf16.h>
#include <stdint.h>
#include <math.h>

#define INF_ 1e10f

__device__ float g_dots [8388608];
__device__ float g_Mt   [1048576];
__device__ float g_WqT  [1048576];
__device__ float g_WkT  [1048576];
__device__ float g_c1   [1024];
__device__ float g_c2   [1024];
__device__ float g_c3   [1];
__device__ float g_steps[64];
__device__ float g_at   [8192];
__device__ float g_bs   [8192];
__device__ float g_gates[8192];
__device__ __nv_bfloat16 g_keyB  [8388608];
__device__ __nv_bfloat16 g_queryB[8388608];
__device__ __nv_bfloat16 g_qmB   [8388608];
__device__ __nv_bfloat16 g_MtB   [1048576];
__device__ __nv_bfloat16 g_WqTB  [1048576];
__device__ __nv_bfloat16 g_WkTB  [1048576];

// ---------- helpers ----------
__device__ __forceinline__ uint32_t pkbf(float a, float b) {
    __nv_bfloat162 t = __halves2bfloat162(__float2bfloat16(a), __float2bfloat16(b));
    return *reinterpret_cast<uint32_t*>(&t);
}
__device__ __forceinline__ float wsum(float v) {
    #pragma unroll
    for (int o = 16; o; o >>= 1) v += __shfl_xor_sync(0xffffffffu, v, o);
    return v;
}
__device__ __forceinline__ float wmax(float v) {
    #pragma unroll
    for (int o = 16; o; o >>= 1) v = fmaxf(v, __shfl_xor_sync(0xffffffffu, v, o));
    return v;
}
__device__ float bsum(float v, float* sb) {
    int lane = threadIdx.x & 31, w = threadIdx.x >> 5, nw = (blockDim.x + 31) >> 5;
    v = wsum(v);
    if (lane == 0) sb[w] = v;
    __syncthreads();
    v = (threadIdx.x < nw) ? sb[threadIdx.x] : 0.f;
    if (w == 0) v = wsum(v);
    if (threadIdx.x == 0) sb[0] = v;
    __syncthreads();
    v = sb[0];
    __syncthreads();
    return v;
}
__device__ float bmax(float v, float* sb) {
    int lane = threadIdx.x & 31, w = threadIdx.x >> 5, nw = (blockDim.x + 31) >> 5;
    v = wmax(v);
    if (lane == 0) sb[w] = v;
    __syncthreads();
    v = (threadIdx.x < nw) ? sb[threadIdx.x] : -INFINITY;
    if (w == 0) v = wmax(v);
    if (threadIdx.x == 0) sb[0] = v;
    __syncthreads();
    v = sb[0];
    __syncthreads();
    return v;
}

// ---------- small kernels ----------
__global__ void k_cvt(const float* __restrict__ in, __nv_bfloat16* __restrict__ o, int n4) {
    int i = blockIdx.x * blockDim.x + threadIdx.x;
    if (i >= n4) return;
    float4 v = ((const float4*)in)[i];
    uint2 p;
    p.x = pkbf(v.x, v.y);
    p.y = pkbf(v.z, v.w);
    *(uint2*)(o + (size_t)i * 4) = p;
}

// transpose Wq (z=0) / Wk (z=1) -> fp32 + bf16; also zero g_Mt (128 float4/block)
__global__ void k_transp2(const float* __restrict__ Wq, const float* __restrict__ Wk, int D) {
    __shared__ float t[32][33];
    const float* in = blockIdx.z ? Wk : Wq;
    float* outp = blockIdx.z ? g_WkT : g_WqT;
    __nv_bfloat16* outb = blockIdx.z ? g_WkTB : g_WqTB;
    int x0 = blockIdx.x * 32, y0 = blockIdx.y * 32;
    int tx = threadIdx.x, ty = threadIdx.y;
    int tid = ty * 32 + tx;
    int bid = blockIdx.x + 32 * (blockIdx.y + 32 * blockIdx.z);
    if (tid < 128)
        ((float4*)g_Mt)[(size_t)bid * 128 + tid] = make_float4(0.f, 0.f, 0.f, 0.f);
    #pragma unroll
    for (int j = 0; j < 32; j += 8)
        t[ty + j][tx] = in[(size_t)(y0 + ty + j) * D + x0 + tx];
    __syncthreads();
    #pragma unroll
    for (int j = 0; j < 32; j += 8) {
        float v = t[tx][ty + j];
        size_t idx = (size_t)(x0 + ty + j) * D + y0 + tx;
        outp[idx] = v;
        outb[idx] = __float2bfloat16(v);
    }
}

// c1[e], c2[e]; block 0: c3; blocks 0..B-1: steps[b]
__global__ void k_cvecR(const float* __restrict__ bq, const float* __restrict__ bk,
                        const float* __restrict__ ms, const float* __restrict__ mt,
                        int D, int B, int S, int T) {
    int e = blockIdx.x;
    __shared__ float sb[32];
    const float4* r1 = (const float4*)(g_WqT + (size_t)e * D);
    const float4* r2 = (const float4*)(g_WkT + (size_t)e * D);
    float s1 = 0.f, s2 = 0.f, s3 = 0.f;
    for (int i = threadIdx.x; i < D / 4; i += blockDim.x) {
        float4 a = r1[i], c = *(const float4*)(bk + i * 4);
        s1 += a.x * c.x + a.y * c.y + a.z * c.z + a.w * c.w;
        float4 b2 = r2[i], d2 = *(const float4*)(bq + i * 4);
        s2 += b2.x * d2.x + b2.y * d2.y + b2.z * d2.z + b2.w * d2.w;
        if (e == 0) s3 += d2.x * c.x + d2.y * c.y + d2.z * c.z + d2.w * c.w;
    }
    s1 = bsum(s1, sb);
    s2 = bsum(s2, sb);
    if (e == 0) {
        s3 = bsum(s3, sb);
        if (threadIdx.x == 0) g_c3[0] = s3;
    }
    if (threadIdx.x == 0) { g_c1[e] = s1; g_c2[e] = s2; }
    if (e < B) {
        float ssum = 0.f;
        for (int i = threadIdx.x; i < S; i += blockDim.x) ssum += ms[(size_t)e * S + i];
        ssum = bsum(ssum, sb);
        float tsum = 0.f;
        for (int i = threadIdx.x; i < T; i += blockDim.x) tsum += mt[(size_t)e * T + i];
        tsum = bsum(tsum, sb);
        if (threadIdx.x == 0) g_steps[e] = ssum / tsum;
    }
}

__global__ void k_bskey(const float* __restrict__ key, int D) {
    int r = blockIdx.x;
    __shared__ float sb[32];
    float s = 0.f;
    const float4* kr = (const float4*)(key + (size_t)r * D);
    uint2* ob = (uint2*)(g_keyB + (size_t)r * D);
    for (int i = threadIdx.x; i < D / 4; i += blockDim.x) {
        float4 kv = kr[i], cv = *(const float4*)(g_c2 + i * 4);
        s += kv.x * cv.x + kv.y * cv.y + kv.z * cv.z + kv.w * cv.w;
        uint2 p;
        p.x = pkbf(kv.x, kv.y);
        p.y = pkbf(kv.z, kv.w);
        ob[i] = p;
    }
    s = bsum(s, sb);
    if (threadIdx.x == 0) g_bs[r] = s;
}

// ---------- windowed query = l_att @ key, fused gates/at ----------
#define QT 16
__global__ __launch_bounds__(256) void k_query(const float* __restrict__ mask_src,
                                               const float* __restrict__ key,
                                               const float* __restrict__ wg,
                                               const float* __restrict__ bg,
                                               int B, int T, int S, int D) {
    __shared__ float wk[QT][64];
    __shared__ float s_c[QT], s_m[QT], s_inv[QT];
    __shared__ int s_s0[QT], s_s1[QT], sh_lo, sh_hi;
    __shared__ float red1[QT], red2[QT];
    int b = blockIdx.y, t0 = blockIdx.x * QT, tid = threadIdx.x;
    int lane = tid & 31;
    float step = g_steps[b];
    if (tid < QT) {
        red1[tid] = 0.f; red2[tid] = 0.f;
        int t = t0 + tid;
        if (t < T) {
            float c = step * (float)t;
            int ci = (int)lrintf(c);
            ci = min(max(ci, 0), S - 1);
            int a0 = max(0, ci - 16), a1 = min(S - 1, ci + 16);
            float mx = -INFINITY;
            for (int s = a0; s <= a1; s++) {
                float d = (float)s - c;
                mx = fmaxf(mx, -(d * d) / 0.3f - INF_ * (1.0f - mask_src[(size_t)b * S + s]));
            }
            float sum = 0.f;
            for (int s = a0; s <= a1; s++) {
                float d = (float)s - c;
                sum += __expf(-(d * d) / 0.3f - INF_ * (1.0f - mask_src[(size_t)b * S + s]) - mx);
            }
            s_c[tid] = c; s_m[tid] = mx; s_inv[tid] = 1.0f / sum;
            s_s0[tid] = a0; s_s1[tid] = a1;
        } else {
            s_c[tid] = 0.f; s_m[tid] = 0.f; s_inv[tid] = 0.f;
            s_s0[tid] = 1; s_s1[tid] = 0;
        }
    }
    __syncthreads();
    if (tid == 0) {
        int lo = s_s0[0], hi = s_s1[0];
        for (int i = 1; i < QT; i++)
            if (s_s1[i] >= s_s0[i]) { lo = min(lo, s_s0[i]); hi = max(hi, s_s1[i]); }
        sh_lo = lo; sh_hi = hi;
    }
    __syncthreads();
    int lo = sh_lo, hi = sh_hi;
    float4 acc[QT];
    #pragma unroll
    for (int r = 0; r < QT; r++) acc[r] = make_float4(0.f, 0.f, 0.f, 0.f);
    for (int c0 = lo; c0 <= hi; c0 += 64) {
        int cnt = min(64, hi - c0 + 1);
        __syncthreads();
        for (int i = tid; i < QT * 64; i += 256) {
            int tr = i >> 6, j = i & 63, s = c0 + j;
            float w = 0.f;
            if (j < cnt && s >= s_s0[tr] && s <= s_s1[tr]) {
                float d = (float)s - s_c[tr];
                w = __expf(-(d * d) / 0.3f - INF_ * (1.0f - mask_src[(size_t)b * S + s]) - s_m[tr]) * s_inv[tr];
            }
            wk[tr][j] = w;
        }
        __syncthreads();
        for (int j = 0; j < cnt; j++) {
            float4 kv = *(const float4*)(key + ((size_t)b * S + c0 + j) * D + tid * 4);
            #pragma unroll
            for (int r = 0; r < QT; r++) {
                float w = wk[r][j];
                acc[r].x = fmaf(w, kv.x, acc[r].x);
                acc[r].y = fmaf(w, kv.y, acc[r].y);
                acc[r].z = fmaf(w, kv.z, acc[r].z);
                acc[r].w = fmaf(w, kv.w, acc[r].w);
            }
        }
        __syncthreads();
    }
    float4 wgv = *(const float4*)(wg + tid * 4);
    float4 c1v = *(const float4*)(g_c1 + tid * 4);
    #pragma unroll
    for (int r = 0; r < QT; r++) {
        int t = t0 + r;
        if (t < T) {
            size_t base = ((size_t)b * T + t) * D + tid * 4;
            uint2 p;
            p.x = pkbf(acc[r].x, acc[r].y);
            p.y = pkbf(acc[r].z, acc[r].w);
            *(uint2*)(g_queryB + base) = p;
        }
        float p1 = acc[r].x * wgv.x + acc[r].y * wgv.y + acc[r].z * wgv.z + acc[r].w * wgv.w;
        float p2 = acc[r].x * c1v.x + acc[r].y * c1v.y + acc[r].z * c1v.z + acc[r].w * c1v.w;
        p1 = wsum(p1);
        p2 = wsum(p2);
        if (lane == 0) { atomicAdd(&red1[r], p1); atomicAdd(&red2[r], p2); }
    }
    __syncthreads();
    if (tid < QT) {
        int t = t0 + tid;
        if (t < T) {
            g_gates[(size_t)b * T + t] = 1.0f / (1.0f + __expf(-(red1[tid] + bg[0])));
            g_at[(size_t)b * T + t] = red2[tid];
        }
    }
}

// ---------- mma wrappers ----------
__device__ __forceinline__ void mma_bf16(float* c, const uint32_t* a, const uint32_t* b) {
    asm volatile("mma.sync.aligned.m16n8k16.row.col.f32.bf16.bf16.f32 "
                 "{%0,%1,%2,%3},{%4,%5,%6,%7},{%8,%9},{%0,%1,%2,%3};"
                 : "+f"(c[0]), "+f"(c[1]), "+f"(c[2]), "+f"(c[3])
                 : "r"(a[0]), "r"(a[1]), "r"(a[2]), "r"(a[3]), "r"(b[0]), "r"(b[1]));
}
__device__ __forceinline__ void cpa16(uint32_t saddr, const void* g) {
    asm volatile("cp.async.cg.shared.global [%0], [%1], 16;" :: "r"(saddr), "l"(g));
}
__device__ __forceinline__ void ldsm4(uint32_t* r, uint32_t addr) {
    asm volatile("ldmatrix.sync.aligned.m8n8.x4.shared.b16 {%0,%1,%2,%3}, [%4];"
                 : "=r"(r[0]), "=r"(r[1]), "=r"(r[2]), "=r"(r[3]) : "r"(addr));
}

// ---------- bf16 NT GEMM: 128x128 CTA, 4 warps of 64x64, 4-stage cp.async ----------
// outmode: 0 = fp32 store, 1 = bf16 store, 2 = fp32 atomicAdd (split-K)
#define BQ 40
#define STG 4
#define SPITCH (128 * BQ)
#define GEMM_SMEM (STG * SPITCH * 2 * 2)
__global__ __launch_bounds__(128, 2) void k_bfgemm(
    const __nv_bfloat16* __restrict__ A, const __nv_bfloat16* __restrict__ B, void* __restrict__ Cout,
    int K, int lda, int ldb, int ldc,
    long long Abat, long long Bbat, long long Cbat, int outmode,
    const float* __restrict__ rowadd, int rowbat,
    const float* __restrict__ coladd, int colbat,
    const float* __restrict__ scalaradd)
{
    extern __shared__ __align__(16) __nv_bfloat16 dsm[];
    __nv_bfloat16* Asb = dsm;
    __nv_bfloat16* Bsb = dsm + STG * SPITCH;
    int tid = threadIdx.x, lane = tid & 31, wid = tid >> 5;
    int bz = blockIdx.z;
    A += Abat * bz; B += Bbat * bz;
    int m0 = blockIdx.y * 128, n0 = blockIdx.x * 128;
    int wm = (wid & 1) * 64, wn = (wid >> 1) * 64;
    float acc[4][8][4] = {};
    const __nv_bfloat16* agp = A + (size_t)(m0 + tid) * lda;
    const __nv_bfloat16* bgp = B + (size_t)(n0 + tid) * ldb;
    int nk = K >> 5;
    int soff = tid * BQ;
    #define LTB(kt, st) do { int _k = (kt) * 32; int _o = (st) * SPITCH + soff; \
        cpa16((uint32_t)__cvta_generic_to_shared(Asb + _o), agp + _k); \
        cpa16((uint32_t)__cvta_generic_to_shared(Asb + _o + 8), agp + _k + 8); \
        cpa16((uint32_t)__cvta_generic_to_shared(Asb + _o + 16), agp + _k + 16); \
        cpa16((uint32_t)__cvta_generic_to_shared(Asb + _o + 24), agp + _k + 24); \
        cpa16((uint32_t)__cvta_generic_to_shared(Bsb + _o), bgp + _k); \
        cpa16((uint32_t)__cvta_generic_to_shared(Bsb + _o + 8), bgp + _k + 8); \
        cpa16((uint32_t)__cvta_generic_to_shared(Bsb + _o + 16), bgp + _k + 16); \
        cpa16((uint32_t)__cvta_generic_to_shared(Bsb + _o + 24), bgp + _k + 24); \
    } while (0)

    #pragma unroll
    for (int i = 0; i < STG - 1; i++) {
        if (i < nk) LTB(i, i);
        asm volatile("cp.async.commit_group;");
    }
    int arow = (lane & 15), aoffb = (lane >> 4) * 8;
    int gq = lane >> 3;
    int brow = (gq >> 1) * 8 + (lane & 7), boffb = (gq & 1) * 8;
    for (int kt = 0; kt < nk; kt++) {
        int st = kt & (STG - 1);
        asm volatile("cp.async.wait_group %0;" :: "n"(STG - 2));
        __syncthreads();
        if (kt + STG - 1 < nk) LTB(kt + STG - 1, (kt + STG - 1) & (STG - 1));
        asm volatile("cp.async.commit_group;");
        const __nv_bfloat16* Ast = Asb + st * SPITCH;
        const __nv_bfloat16* Bst = Bsb + st * SPITCH;
        #pragma unroll
        for (int kk = 0; kk < 32; kk += 16) {
            uint32_t ar[4][4], br[8][2];
            #pragma unroll
            for (int mi = 0; mi < 4; mi++)
                ldsm4(ar[mi], (uint32_t)__cvta_generic_to_shared(
                    Ast + (wm + mi * 16 + arow) * BQ + kk + aoffb));
            #pragma unroll
            for (int nj = 0; nj < 4; nj++) {
                uint32_t t4[4];
                ldsm4(t4, (uint32_t)__cvta_generic_to_shared(
                    Bst + (wn + nj * 16 + brow) * BQ + kk + boffb));
                br[nj * 2][0] = t4[0];
                br[nj * 2][1] = t4[1];
                br[nj * 2 + 1][0] = t4[2];
                br[nj * 2 + 1][1] = t4[3];
            }
            #pragma unroll
            for (int mi = 0; mi < 4; mi++)
                #pragma unroll
                for (int ni = 0; ni < 8; ni++)
                    mma_bf16(acc[mi][ni], ar[mi], br[ni]);
        }
    }
    float sc = scalaradd ? scalaradd[0] : 0.f;
    #pragma unroll
    for (int mi = 0; mi < 4; mi++) {
        int r0 = m0 + wm + mi * 16 + (lane >> 2);
        float ra0 = sc + (rowadd ? rowadd[(size_t)rowbat * bz + r0] : 0.f);
        float ra1 = sc + (rowadd ? rowadd[(size_t)rowbat * bz + r0 + 8] : 0.f);
        #pragma unroll
        for (int ni = 0; ni < 8; ni++) {
            int c0 = n0 + wn + ni * 8 + (lane & 3) * 2;
            float cb0 = coladd ? coladd[(size_t)colbat * bz + c0] : 0.f;
            float cb1 = coladd ? coladd[(size_t)colbat * bz + c0 + 1] : 0.f;
            float v00 = acc[mi][ni][0] + ra0 + cb0, v01 = acc[mi][ni][1] + ra0 + cb1;
            float v10 = acc[mi][ni][2] + ra1 + cb0, v11 = acc[mi][ni][3] + ra1 + cb1;
            if (outmode == 1) {
                __nv_bfloat16* Cb = (__nv_bfloat16*)Cout + Cbat * bz;
                *(uint32_t*)(Cb + (size_t)r0 * ldc + c0) = pkbf(v00, v01);
                *(uint32_t*)(Cb + (size_t)(r0 + 8) * ldc + c0) = pkbf(v10, v11);
            } else if (outmode == 0) {
                float* Cf = (float*)Cout + Cbat * bz;
                *(float2*)(Cf + (size_t)r0 * ldc + c0) = make_float2(v00, v01);
                *(float2*)(Cf + (size_t)(r0 + 8) * ldc + c0) = make_float2(v10, v11);
            } else {
                float* Cf = (float*)Cout;
                atomicAdd(Cf + (size_t)r0 * ldc + c0, v00);
                atomicAdd(Cf + (size_t)r0 * ldc + c0 + 1, v01);
                atomicAdd(Cf + (size_t)(r0 + 8) * ldc + c0, v10);
                atomicAdd(Cf + (size_t)(r0 + 8) * ldc + c0 + 1, v11);
            }
        }
    }
}

// ---------- final ----------
__global__ void k_final(const float* __restrict__ mask_src, float* __restrict__ out,
                        const float* __restrict__ dots, int B, int T, int S, float invscale) {
    int bt = blockIdx.x;
    int b = bt / T, t = bt - b * T;
    extern __shared__ float sm[];
    float* sp = sm;
    float* sl = sm + S;
    __shared__ float sred[32];
    float c = g_steps[b] * (float)t;
    float lmax = -INFINITY, qmax = -INFINITY;
    for (int s = threadIdx.x; s < S; s += blockDim.x) {
        float msk = 1.0f - mask_src[(size_t)b * S + s];
        float d = (float)s - c;
        float lg = -(d * d) / 0.3f - INF_ * msk;
        sl[s] = lg;
        lmax = fmaxf(lmax, lg);
        float x = (dots[(size_t)bt * S + s] - msk * INF_) * invscale;
        sp[s] = x;
        qmax = fmaxf(qmax, x);
    }
    lmax = bmax(lmax, sred);
    qmax = bmax(qmax, sred);
    float lsum = 0.f, qsum = 0.f;
    for (int s = threadIdx.x; s < S; s += blockDim.x) {
        float el = __expf(sl[s] - lmax);
        sl[s] = el;
        lsum += el;
        float eq = __expf(sp[s] - qmax);
        sp[s] = eq;
        qsum += eq;
    }
    lsum = bsum(lsum, sred);
    qsum = bsum(qsum, sred);
    float linv = 1.0f / lsum, qinv = 1.0f / qsum;
    float g = g_gates[bt];
    for (int s = threadIdx.x; s < S; s += blockDim.x)
        out[(size_t)bt * S + s] = (1.0f - g) * (sp[s] * qinv) + g * (sl[s] * linv);
}

// ---------- launch ----------
extern "C" void kernel_launch(void* const* d_in, const int* in_sizes, int n_in,
                              void* d_out, int out_size) {
    const float* key      = (const float*)d_in[0];
    const float* mask_src = (const float*)d_in[1];
    const float* mask_trg = (const float*)d_in[2];
    const float* Wq       = (const float*)d_in[3];
    const float* bq       = (const float*)d_in[4];
    const float* Wk       = (const float*)d_in[5];
    const float* bk       = (const float*)d_in[6];
    const float* wg       = (const float*)d_in[7];
    const float* bg       = (const float*)d_in[8];
    float* out = (float*)d_out;

    int D  = in_sizes[4];
    int BT = in_sizes[2];
    int S  = out_size / BT;
    int B  = in_sizes[1] / S;
    int T  = BT / B;

    float *p_Mt, *p_c3, *p_at, *p_bs, *p_dots;
    __nv_bfloat16 *p_keyB, *p_queryB, *p_qmB, *p_MtB, *p_WqTB, *p_WkTB;
    cudaGetSymbolAddress((void**)&p_Mt,    g_Mt);
    cudaGetSymbolAddress((void**)&p_c3,    g_c3);
    cudaGetSymbolAddress((void**)&p_at,    g_at);
    cudaGetSymbolAddress((void**)&p_bs,    g_bs);
    cudaGetSymbolAddress((void**)&p_dots,  g_dots);
    cudaGetSymbolAddress((void**)&p_keyB,  g_keyB);
    cudaGetSymbolAddress((void**)&p_queryB, g_queryB);
    cudaGetSymbolAddress((void**)&p_qmB,   g_qmB);
    cudaGetSymbolAddress((void**)&p_MtB,   g_MtB);
    cudaGetSymbolAddress((void**)&p_WqTB,  g_WqTB);
    cudaGetSymbolAddress((void**)&p_WkTB,  g_WkTB);

    cudaFuncSetAttribute(k_bfgemm, cudaFuncAttributeMaxDynamicSharedMemorySize, GEMM_SMEM);

    // 1: transpose Wq/Wk (+ zero Mt)
    {
        dim3 tb(32, 8);
        dim3 g(D / 32, D / 32, 2);
        k_transp2<<<g, tb>>>(Wq, Wk, D);
    }
    // 2: c1/c2/c3 + steps
    k_cvecR<<<D, 128>>>(bq, bk, mask_src, mask_trg, D, B, S, T);
    // 3: windowed query + gates/at
    {
        dim3 g((T + QT - 1) / QT, B);
        k_query<<<g, 256>>>(mask_src, key, wg, bg, B, T, S, D);
    }
    // 4: Mt split-K x4 (fp32 atomic accumulate)
    {
        dim3 g(D / 128, D / 128, 4);
        k_bfgemm<<<g, 128, GEMM_SMEM>>>(p_WkTB, p_WqTB, p_Mt, D / 4, D, D, D,
                                        D / 4, D / 4, 0, 2, nullptr, 0, nullptr, 0, nullptr);
    }
    // 5: Mt -> bf16
    k_cvt<<<(D * D / 4 + 255) / 256, 256>>>(p_Mt, p_MtB, D * D / 4);
    // 6 (ncu capture): qmB = queryB @ MtB^T
    {
        dim3 g(D / 128, BT / 128, 1);
        k_bfgemm<<<g, 128, GEMM_SMEM>>>(p_queryB, p_MtB, p_qmB, D, D, D, D,
                                        0, 0, 0, 1, nullptr, 0, nullptr, 0, nullptr);
    }
    // 7
    k_bskey<<<B * S, 128>>>(key, D);
    // 8: dots = qmB @ keyB^T + at + bs + c3
    {
        dim3 g(S / 128, T / 128, B);
        k_bfgemm<<<g, 128, GEMM_SMEM>>>(p_qmB, p_keyB, p_dots, D, D, D, S,
                                        (long long)T * D, (long long)S * D, (long long)T * S, 0,
                                        p_at, T, p_bs, S, p_c3);
    }
    // 9
    k_final<<<B * T, 256, 2 * S * (int)sizeof(float)>>>(mask_src, out, p_dots, B, T, S,
                                                        1.0f / sqrtf((float)D));
}

// round 12
// speedup vs baseline: 1.0858x; 1.0858x over previous
#include <cuda_runtime.h>
#include <cuda_bf16.h>
#include <stdint.h>
#include <math.h>

#define INF_ 1e10f

__device__ float g_dots [8388608];
__device__ float g_Mt   [1048576];
__device__ float g_WqT  [1048576];
__device__ float g_WkT  [1048576];
__device__ float g_c1   [1024];
__device__ float g_c2   [1024];
__device__ float g_c3   [1];
__device__ float g_steps[64];
__device__ float g_at   [8192];
__device__ float g_bs   [8192];
__device__ float g_gates[8192];
__device__ __nv_bfloat16 g_keyB  [8388608];
__device__ __nv_bfloat16 g_queryB[8388608];
__device__ __nv_bfloat16 g_qmB   [8388608];
__device__ __nv_bfloat16 g_MtB   [1048576];
__device__ __nv_bfloat16 g_WqTB  [1048576];
__device__ __nv_bfloat16 g_WkTB  [1048576];

// ---------- helpers ----------
__device__ __forceinline__ uint32_t pkbf(float a, float b) {
    __nv_bfloat162 t = __halves2bfloat162(__float2bfloat16(a), __float2bfloat16(b));
    return *reinterpret_cast<uint32_t*>(&t);
}
__device__ __forceinline__ float wsum(float v) {
    #pragma unroll
    for (int o = 16; o; o >>= 1) v += __shfl_xor_sync(0xffffffffu, v, o);
    return v;
}
__device__ __forceinline__ float wmax(float v) {
    #pragma unroll
    for (int o = 16; o; o >>= 1) v = fmaxf(v, __shfl_xor_sync(0xffffffffu, v, o));
    return v;
}
__device__ float bsum(float v, float* sb) {
    int lane = threadIdx.x & 31, w = threadIdx.x >> 5, nw = (blockDim.x + 31) >> 5;
    v = wsum(v);
    if (lane == 0) sb[w] = v;
    __syncthreads();
    v = (threadIdx.x < nw) ? sb[threadIdx.x] : 0.f;
    if (w == 0) v = wsum(v);
    if (threadIdx.x == 0) sb[0] = v;
    __syncthreads();
    v = sb[0];
    __syncthreads();
    return v;
}
__device__ float bmax(float v, float* sb) {
    int lane = threadIdx.x & 31, w = threadIdx.x >> 5, nw = (blockDim.x + 31) >> 5;
    v = wmax(v);
    if (lane == 0) sb[w] = v;
    __syncthreads();
    v = (threadIdx.x < nw) ? sb[threadIdx.x] : -INFINITY;
    if (w == 0) v = wmax(v);
    if (threadIdx.x == 0) sb[0] = v;
    __syncthreads();
    v = sb[0];
    __syncthreads();
    return v;
}

// ---------- small kernels ----------
__global__ void k_cvt(const float* __restrict__ in, __nv_bfloat16* __restrict__ o, int n4) {
    int i = blockIdx.x * blockDim.x + threadIdx.x;
    if (i >= n4) return;
    float4 v = ((const float4*)in)[i];
    uint2 p;
    p.x = pkbf(v.x, v.y);
    p.y = pkbf(v.z, v.w);
    *(uint2*)(o + (size_t)i * 4) = p;
}

// transpose Wq (z=0) / Wk (z=1) -> fp32 + bf16; also zero g_Mt
__global__ void k_transp2(const float* __restrict__ Wq, const float* __restrict__ Wk, int D) {
    __shared__ float t[32][33];
    const float* in = blockIdx.z ? Wk : Wq;
    float* outp = blockIdx.z ? g_WkT : g_WqT;
    __nv_bfloat16* outb = blockIdx.z ? g_WkTB : g_WqTB;
    int x0 = blockIdx.x * 32, y0 = blockIdx.y * 32;
    int tx = threadIdx.x, ty = threadIdx.y;
    int tid = ty * 32 + tx;
    int bid = blockIdx.x + 32 * (blockIdx.y + 32 * blockIdx.z);
    if (tid < 128)
        ((float4*)g_Mt)[(size_t)bid * 128 + tid] = make_float4(0.f, 0.f, 0.f, 0.f);
    #pragma unroll
    for (int j = 0; j < 32; j += 8)
        t[ty + j][tx] = in[(size_t)(y0 + ty + j) * D + x0 + tx];
    __syncthreads();
    #pragma unroll
    for (int j = 0; j < 32; j += 8) {
        float v = t[tx][ty + j];
        size_t idx = (size_t)(x0 + ty + j) * D + y0 + tx;
        outp[idx] = v;
        outb[idx] = __float2bfloat16(v);
    }
}

// c1[e], c2[e]; block 0: c3; blocks 0..B-1: steps[b]
__global__ void k_cvecR(const float* __restrict__ bq, const float* __restrict__ bk,
                        const float* __restrict__ ms, const float* __restrict__ mt,
                        int D, int B, int S, int T) {
    int e = blockIdx.x;
    __shared__ float sb[32];
    const float4* r1 = (const float4*)(g_WqT + (size_t)e * D);
    const float4* r2 = (const float4*)(g_WkT + (size_t)e * D);
    float s1 = 0.f, s2 = 0.f, s3 = 0.f;
    for (int i = threadIdx.x; i < D / 4; i += blockDim.x) {
        float4 a = r1[i], c = *(const float4*)(bk + i * 4);
        s1 += a.x * c.x + a.y * c.y + a.z * c.z + a.w * c.w;
        float4 b2 = r2[i], d2 = *(const float4*)(bq + i * 4);
        s2 += b2.x * d2.x + b2.y * d2.y + b2.z * d2.z + b2.w * d2.w;
        if (e == 0) s3 += d2.x * c.x + d2.y * c.y + d2.z * c.z + d2.w * c.w;
    }
    s1 = bsum(s1, sb);
    s2 = bsum(s2, sb);
    if (e == 0) {
        s3 = bsum(s3, sb);
        if (threadIdx.x == 0) g_c3[0] = s3;
    }
    if (threadIdx.x == 0) { g_c1[e] = s1; g_c2[e] = s2; }
    if (e < B) {
        float ssum = 0.f;
        for (int i = threadIdx.x; i < S; i += blockDim.x) ssum += ms[(size_t)e * S + i];
        ssum = bsum(ssum, sb);
        float tsum = 0.f;
        for (int i = threadIdx.x; i < T; i += blockDim.x) tsum += mt[(size_t)e * T + i];
        tsum = bsum(tsum, sb);
        if (threadIdx.x == 0) g_steps[e] = ssum / tsum;
    }
}

__global__ void k_bskey(const float* __restrict__ key, int D) {
    int r = blockIdx.x;
    __shared__ float sb[32];
    float s = 0.f;
    const float4* kr = (const float4*)(key + (size_t)r * D);
    uint2* ob = (uint2*)(g_keyB + (size_t)r * D);
    for (int i = threadIdx.x; i < D / 4; i += blockDim.x) {
        float4 kv = kr[i], cv = *(const float4*)(g_c2 + i * 4);
        s += kv.x * cv.x + kv.y * cv.y + kv.z * cv.z + kv.w * cv.w;
        uint2 p;
        p.x = pkbf(kv.x, kv.y);
        p.y = pkbf(kv.z, kv.w);
        ob[i] = p;
    }
    s = bsum(s, sb);
    if (threadIdx.x == 0) g_bs[r] = s;
}

// ---------- windowed query = l_att @ key, fused gates/at ----------
#define QT 16
__global__ __launch_bounds__(256) void k_query(const float* __restrict__ mask_src,
                                               const float* __restrict__ key,
                                               const float* __restrict__ wg,
                                               const float* __restrict__ bg,
                                               int B, int T, int S, int D) {
    __shared__ float wk[QT][64];
    __shared__ float s_c[QT], s_m[QT], s_inv[QT];
    __shared__ int s_s0[QT], s_s1[QT], sh_lo, sh_hi;
    __shared__ float red1[QT], red2[QT];
    int b = blockIdx.y, t0 = blockIdx.x * QT, tid = threadIdx.x;
    int lane = tid & 31;
    float step = g_steps[b];
    if (tid < QT) {
        red1[tid] = 0.f; red2[tid] = 0.f;
        int t = t0 + tid;
        if (t < T) {
            float c = step * (float)t;
            int ci = (int)lrintf(c);
            ci = min(max(ci, 0), S - 1);
            int a0 = max(0, ci - 16), a1 = min(S - 1, ci + 16);
            float mx = -INFINITY;
            for (int s = a0; s <= a1; s++) {
                float d = (float)s - c;
                mx = fmaxf(mx, -(d * d) / 0.3f - INF_ * (1.0f - mask_src[(size_t)b * S + s]));
            }
            float sum = 0.f;
            for (int s = a0; s <= a1; s++) {
                float d = (float)s - c;
                sum += __expf(-(d * d) / 0.3f - INF_ * (1.0f - mask_src[(size_t)b * S + s]) - mx);
            }
            s_c[tid] = c; s_m[tid] = mx; s_inv[tid] = 1.0f / sum;
            s_s0[tid] = a0; s_s1[tid] = a1;
        } else {
            s_c[tid] = 0.f; s_m[tid] = 0.f; s_inv[tid] = 0.f;
            s_s0[tid] = 1; s_s1[tid] = 0;
        }
    }
    __syncthreads();
    if (tid == 0) {
        int lo = s_s0[0], hi = s_s1[0];
        for (int i = 1; i < QT; i++)
            if (s_s1[i] >= s_s0[i]) { lo = min(lo, s_s0[i]); hi = max(hi, s_s1[i]); }
        sh_lo = lo; sh_hi = hi;
    }
    __syncthreads();
    int lo = sh_lo, hi = sh_hi;
    float4 acc[QT];
    #pragma unroll
    for (int r = 0; r < QT; r++) acc[r] = make_float4(0.f, 0.f, 0.f, 0.f);
    for (int c0 = lo; c0 <= hi; c0 += 64) {
        int cnt = min(64, hi - c0 + 1);
        __syncthreads();
        for (int i = tid; i < QT * 64; i += 256) {
            int tr = i >> 6, j = i & 63, s = c0 + j;
            float w = 0.f;
            if (j < cnt && s >= s_s0[tr] && s <= s_s1[tr]) {
                float d = (float)s - s_c[tr];
                w = __expf(-(d * d) / 0.3f - INF_ * (1.0f - mask_src[(size_t)b * S + s]) - s_m[tr]) * s_inv[tr];
            }
            wk[tr][j] = w;
        }
        __syncthreads();
        for (int j = 0; j < cnt; j++) {
            float4 kv = *(const float4*)(key + ((size_t)b * S + c0 + j) * D + tid * 4);
            #pragma unroll
            for (int r = 0; r < QT; r++) {
                float w = wk[r][j];
                acc[r].x = fmaf(w, kv.x, acc[r].x);
                acc[r].y = fmaf(w, kv.y, acc[r].y);
                acc[r].z = fmaf(w, kv.z, acc[r].z);
                acc[r].w = fmaf(w, kv.w, acc[r].w);
            }
        }
        __syncthreads();
    }
    float4 wgv = *(const float4*)(wg + tid * 4);
    float4 c1v = *(const float4*)(g_c1 + tid * 4);
    #pragma unroll
    for (int r = 0; r < QT; r++) {
        int t = t0 + r;
        if (t < T) {
            size_t base = ((size_t)b * T + t) * D + tid * 4;
            uint2 p;
            p.x = pkbf(acc[r].x, acc[r].y);
            p.y = pkbf(acc[r].z, acc[r].w);
            *(uint2*)(g_queryB + base) = p;
        }
        float p1 = acc[r].x * wgv.x + acc[r].y * wgv.y + acc[r].z * wgv.z + acc[r].w * wgv.w;
        float p2 = acc[r].x * c1v.x + acc[r].y * c1v.y + acc[r].z * c1v.z + acc[r].w * c1v.w;
        p1 = wsum(p1);
        p2 = wsum(p2);
        if (lane == 0) { atomicAdd(&red1[r], p1); atomicAdd(&red2[r], p2); }
    }
    __syncthreads();
    if (tid < QT) {
        int t = t0 + tid;
        if (t < T) {
            g_gates[(size_t)b * T + t] = 1.0f / (1.0f + __expf(-(red1[tid] + bg[0])));
            g_at[(size_t)b * T + t] = red2[tid];
        }
    }
}

// ---------- mma wrappers ----------
__device__ __forceinline__ void mma_bf16(float* c, const uint32_t* a, const uint32_t* b) {
    asm volatile("mma.sync.aligned.m16n8k16.row.col.f32.bf16.bf16.f32 "
                 "{%0,%1,%2,%3},{%4,%5,%6,%7},{%8,%9},{%0,%1,%2,%3};"
                 : "+f"(c[0]), "+f"(c[1]), "+f"(c[2]), "+f"(c[3])
                 : "r"(a[0]), "r"(a[1]), "r"(a[2]), "r"(a[3]), "r"(b[0]), "r"(b[1]));
}
__device__ __forceinline__ void cpa16(uint32_t saddr, const void* g) {
    asm volatile("cp.async.cg.shared.global [%0], [%1], 16;" :: "r"(saddr), "l"(g));
}
__device__ __forceinline__ void ldsm4(uint32_t* r, uint32_t addr) {
    asm volatile("ldmatrix.sync.aligned.m8n8.x4.shared.b16 {%0,%1,%2,%3}, [%4];"
                 : "=r"(r[0]), "=r"(r[1]), "=r"(r[2]), "=r"(r[3]) : "r"(addr));
}

// ---------- bf16 NT GEMM: 128x128 CTA, 8 warps of 64x32, K-chunk 64, 3 stages ----------
// outmode: 0 = fp32 store, 1 = bf16 store, 2 = fp32 atomicAdd (split-K)
#define BQ 72
#define STG 3
#define SPITCH (128 * BQ)
#define GEMM_SMEM (STG * SPITCH * 2 * 2)
__global__ __launch_bounds__(256, 2) void k_bfgemm(
    const __nv_bfloat16* __restrict__ A, const __nv_bfloat16* __restrict__ B, void* __restrict__ Cout,
    int K, int lda, int ldb, int ldc,
    long long Abat, long long Bbat, long long Cbat, int outmode,
    const float* __restrict__ rowadd, int rowbat,
    const float* __restrict__ coladd, int colbat,
    const float* __restrict__ scalaradd)
{
    extern __shared__ __align__(16) __nv_bfloat16 dsm[];
    __nv_bfloat16* Asb = dsm;
    __nv_bfloat16* Bsb = dsm + STG * SPITCH;
    int tid = threadIdx.x, lane = tid & 31, wid = tid >> 5;
    int bz = blockIdx.z;
    A += Abat * bz; B += Bbat * bz;
    int m0 = blockIdx.y * 128, n0 = blockIdx.x * 128;
    int wm = (wid & 1) * 64, wn = (wid >> 1) * 32;
    float acc[4][4][4] = {};
    int lrow = tid >> 1, lcol = (tid & 1) * 32;
    const __nv_bfloat16* agp = A + (size_t)(m0 + lrow) * lda + lcol;
    const __nv_bfloat16* bgp = B + (size_t)(n0 + lrow) * ldb + lcol;
    int nk = K >> 6;   // 64 K per tile
    int soff = lrow * BQ + lcol;
    #define LTB(kt, st) do { int _k = (kt) * 64; int _o = (st) * SPITCH + soff; \
        cpa16((uint32_t)__cvta_generic_to_shared(Asb + _o), agp + _k); \
        cpa16((uint32_t)__cvta_generic_to_shared(Asb + _o + 8), agp + _k + 8); \
        cpa16((uint32_t)__cvta_generic_to_shared(Asb + _o + 16), agp + _k + 16); \
        cpa16((uint32_t)__cvta_generic_to_shared(Asb + _o + 24), agp + _k + 24); \
        cpa16((uint32_t)__cvta_generic_to_shared(Bsb + _o), bgp + _k); \
        cpa16((uint32_t)__cvta_generic_to_shared(Bsb + _o + 8), bgp + _k + 8); \
        cpa16((uint32_t)__cvta_generic_to_shared(Bsb + _o + 16), bgp + _k + 16); \
        cpa16((uint32_t)__cvta_generic_to_shared(Bsb + _o + 24), bgp + _k + 24); \
    } while (0)

    #pragma unroll
    for (int i = 0; i < STG - 1; i++) {
        if (i < nk) LTB(i, i);
        asm volatile("cp.async.commit_group;");
    }
    int arow = (lane & 15), aoffb = (lane >> 4) * 8;
    int gq = lane >> 3;
    int brow = (gq >> 1) * 8 + (lane & 7), boffb = (gq & 1) * 8;
    for (int kt = 0; kt < nk; kt++) {
        int st = kt % STG;
        asm volatile("cp.async.wait_group %0;" :: "n"(STG - 2));
        __syncthreads();
        if (kt + STG - 1 < nk) LTB(kt + STG - 1, (kt + STG - 1) % STG);
        asm volatile("cp.async.commit_group;");
        const __nv_bfloat16* Ast = Asb + st * SPITCH;
        const __nv_bfloat16* Bst = Bsb + st * SPITCH;
        #pragma unroll
        for (int kk = 0; kk < 64; kk += 16) {
            uint32_t ar[4][4], br[4][2];
            #pragma unroll
            for (int mi = 0; mi < 4; mi++)
                ldsm4(ar[mi], (uint32_t)__cvta_generic_to_shared(
                    Ast + (wm + mi * 16 + arow) * BQ + kk + aoffb));
            #pragma unroll
            for (int nj = 0; nj < 2; nj++) {
                uint32_t t4[4];
                ldsm4(t4, (uint32_t)__cvta_generic_to_shared(
                    Bst + (wn + nj * 16 + brow) * BQ + kk + boffb));
                br[nj * 2][0] = t4[0];
                br[nj * 2][1] = t4[1];
                br[nj * 2 + 1][0] = t4[2];
                br[nj * 2 + 1][1] = t4[3];
            }
            #pragma unroll
            for (int mi = 0; mi < 4; mi++)
                #pragma unroll
                for (int ni = 0; ni < 4; ni++)
                    mma_bf16(acc[mi][ni], ar[mi], br[ni]);
        }
    }
    float sc = scalaradd ? scalaradd[0] : 0.f;
    #pragma unroll
    for (int mi = 0; mi < 4; mi++) {
        int r0 = m0 + wm + mi * 16 + (lane >> 2);
        float ra0 = sc + (rowadd ? rowadd[(size_t)rowbat * bz + r0] : 0.f);
        float ra1 = sc + (rowadd ? rowadd[(size_t)rowbat * bz + r0 + 8] : 0.f);
        #pragma unroll
        for (int ni = 0; ni < 4; ni++) {
            int c0 = n0 + wn + ni * 8 + (lane & 3) * 2;
            float cb0 = coladd ? coladd[(size_t)colbat * bz + c0] : 0.f;
            float cb1 = coladd ? coladd[(size_t)colbat * bz + c0 + 1] : 0.f;
            float v00 = acc[mi][ni][0] + ra0 + cb0, v01 = acc[mi][ni][1] + ra0 + cb1;
            float v10 = acc[mi][ni][2] + ra1 + cb0, v11 = acc[mi][ni][3] + ra1 + cb1;
            if (outmode == 1) {
                __nv_bfloat16* Cb = (__nv_bfloat16*)Cout + Cbat * bz;
                *(uint32_t*)(Cb + (size_t)r0 * ldc + c0) = pkbf(v00, v01);
                *(uint32_t*)(Cb + (size_t)(r0 + 8) * ldc + c0) = pkbf(v10, v11);
            } else if (outmode == 0) {
                float* Cf = (float*)Cout + Cbat * bz;
                *(float2*)(Cf + (size_t)r0 * ldc + c0) = make_float2(v00, v01);
                *(float2*)(Cf + (size_t)(r0 + 8) * ldc + c0) = make_float2(v10, v11);
            } else {
                float* Cf = (float*)Cout;
                atomicAdd(Cf + (size_t)r0 * ldc + c0, v00);
                atomicAdd(Cf + (size_t)r0 * ldc + c0 + 1, v01);
                atomicAdd(Cf + (size_t)(r0 + 8) * ldc + c0, v10);
                atomicAdd(Cf + (size_t)(r0 + 8) * ldc + c0 + 1, v11);
            }
        }
    }
}

// ---------- final ----------
__global__ void k_final(const float* __restrict__ mask_src, float* __restrict__ out,
                        const float* __restrict__ dots, int B, int T, int S, float invscale) {
    int bt = blockIdx.x;
    int b = bt / T, t = bt - b * T;
    extern __shared__ float sm[];
    float* sp = sm;
    float* sl = sm + S;
    __shared__ float sred[32];
    float c = g_steps[b] * (float)t;
    float lmax = -INFINITY, qmax = -INFINITY;
    for (int s = threadIdx.x; s < S; s += blockDim.x) {
        float msk = 1.0f - mask_src[(size_t)b * S + s];
        float d = (float)s - c;
        float lg = -(d * d) / 0.3f - INF_ * msk;
        sl[s] = lg;
        lmax = fmaxf(lmax, lg);
        float x = (dots[(size_t)bt * S + s] - msk * INF_) * invscale;
        sp[s] = x;
        qmax = fmaxf(qmax, x);
    }
    lmax = bmax(lmax, sred);
    qmax = bmax(qmax, sred);
    float lsum = 0.f, qsum = 0.f;
    for (int s = threadIdx.x; s < S; s += blockDim.x) {
        float el = __expf(sl[s] - lmax);
        sl[s] = el;
        lsum += el;
        float eq = __expf(sp[s] - qmax);
        sp[s] = eq;
        qsum += eq;
    }
    lsum = bsum(lsum, sred);
    qsum = bsum(qsum, sred);
    float linv = 1.0f / lsum, qinv = 1.0f / qsum;
    float g = g_gates[bt];
    for (int s = threadIdx.x; s < S; s += blockDim.x)
        out[(size_t)bt * S + s] = (1.0f - g) * (sp[s] * qinv) + g * (sl[s] * linv);
}

// ---------- launch ----------
extern "C" void kernel_launch(void* const* d_in, const int* in_sizes, int n_in,
                              void* d_out, int out_size) {
    const float* key      = (const float*)d_in[0];
    const float* mask_src = (const float*)d_in[1];
    const float* mask_trg = (const float*)d_in[2];
    const float* Wq       = (const float*)d_in[3];
    const float* bq       = (const float*)d_in[4];
    const float* Wk       = (const float*)d_in[5];
    const float* bk       = (const float*)d_in[6];
    const float* wg       = (const float*)d_in[7];
    const float* bg       = (const float*)d_in[8];
    float* out = (float*)d_out;

    int D  = in_sizes[4];
    int BT = in_sizes[2];
    int S  = out_size / BT;
    int B  = in_sizes[1] / S;
    int T  = BT / B;

    float *p_Mt, *p_c3, *p_at, *p_bs, *p_dots;
    __nv_bfloat16 *p_keyB, *p_queryB, *p_qmB, *p_MtB, *p_WqTB, *p_WkTB;
    cudaGetSymbolAddress((void**)&p_Mt,    g_Mt);
    cudaGetSymbolAddress((void**)&p_c3,    g_c3);
    cudaGetSymbolAddress((void**)&p_at,    g_at);
    cudaGetSymbolAddress((void**)&p_bs,    g_bs);
    cudaGetSymbolAddress((void**)&p_dots,  g_dots);
    cudaGetSymbolAddress((void**)&p_keyB,  g_keyB);
    cudaGetSymbolAddress((void**)&p_queryB, g_queryB);
    cudaGetSymbolAddress((void**)&p_qmB,   g_qmB);
    cudaGetSymbolAddress((void**)&p_MtB,   g_MtB);
    cudaGetSymbolAddress((void**)&p_WqTB,  g_WqTB);
    cudaGetSymbolAddress((void**)&p_WkTB,  g_WkTB);

    cudaFuncSetAttribute(k_bfgemm, cudaFuncAttributeMaxDynamicSharedMemorySize, GEMM_SMEM);

    // 1: transpose Wq/Wk (+ zero Mt)
    {
        dim3 tb(32, 8);
        dim3 g(D / 32, D / 32, 2);
        k_transp2<<<g, tb>>>(Wq, Wk, D);
    }
    // 2: c1/c2/c3 + steps
    k_cvecR<<<D, 128>>>(bq, bk, mask_src, mask_trg, D, B, S, T);
    // 3: windowed query + gates/at
    {
        dim3 g((T + QT - 1) / QT, B);
        k_query<<<g, 256>>>(mask_src, key, wg, bg, B, T, S, D);
    }
    // 4: Mt split-K x4 (fp32 atomic accumulate)
    {
        dim3 g(D / 128, D / 128, 4);
        k_bfgemm<<<g, 256, GEMM_SMEM>>>(p_WkTB, p_WqTB, p_Mt, D / 4, D, D, D,
                                        D / 4, D / 4, 0, 2, nullptr, 0, nullptr, 0, nullptr);
    }
    // 5: Mt -> bf16
    k_cvt<<<(D * D / 4 + 255) / 256, 256>>>(p_Mt, p_MtB, D * D / 4);
    // 6 (ncu capture): qmB = queryB @ MtB^T
    {
        dim3 g(D / 128, BT / 128, 1);
        k_bfgemm<<<g, 256, GEMM_SMEM>>>(p_queryB, p_MtB, p_qmB, D, D, D, D,
                                        0, 0, 0, 1, nullptr, 0, nullptr, 0, nullptr);
    }
    // 7
    k_bskey<<<B * S, 128>>>(key, D);
    // 8: dots = qmB @ keyB^T + at + bs + c3
    {
        dim3 g(S / 128, T / 128, B);
        k_bfgemm<<<g, 256, GEMM_SMEM>>>(p_qmB, p_keyB, p_dots, D, D, D, S,
                                        (long long)T * D, (long long)S * D, (long long)T * S, 0,
                                        p_at, T, p_bs, S, p_c3);
    }
    // 9
    k_final<<<B * T, 256, 2 * S * (int)sizeof(float)>>>(mask_src, out, p_dots, B, T, S,
                                                        1.0f / sqrtf((float)D));
}

// round 13
// speedup vs baseline: 1.2073x; 1.1119x over previous
#include <cuda_runtime.h>
#include <cuda_bf16.h>
#include <stdint.h>
#include <math.h>

#define INF_ 1e10f

__device__ float g_dots [8388608];
__device__ float g_Mt   [1048576];
__device__ float g_WqT  [1048576];
__device__ float g_WkT  [1048576];
__device__ float g_c1   [1024];
__device__ float g_c2   [1024];
__device__ float g_c3   [1];
__device__ float g_steps[64];
__device__ float g_at   [8192];
__device__ float g_bs   [8192];
__device__ float g_gates[8192];
__device__ __nv_bfloat16 g_keyB  [8388608];
__device__ __nv_bfloat16 g_queryB[8388608];
__device__ __nv_bfloat16 g_qmB   [8388608];
__device__ __nv_bfloat16 g_MtB   [1048576];
__device__ __nv_bfloat16 g_WqTB  [1048576];
__device__ __nv_bfloat16 g_WkTB  [1048576];

// ---------- helpers ----------
__device__ __forceinline__ uint32_t pkbf(float a, float b) {
    __nv_bfloat162 t = __halves2bfloat162(__float2bfloat16(a), __float2bfloat16(b));
    return *reinterpret_cast<uint32_t*>(&t);
}
__device__ __forceinline__ float wsum(float v) {
    #pragma unroll
    for (int o = 16; o; o >>= 1) v += __shfl_xor_sync(0xffffffffu, v, o);
    return v;
}
__device__ __forceinline__ float wmax(float v) {
    #pragma unroll
    for (int o = 16; o; o >>= 1) v = fmaxf(v, __shfl_xor_sync(0xffffffffu, v, o));
    return v;
}
__device__ float bsum(float v, float* sb) {
    int lane = threadIdx.x & 31, w = threadIdx.x >> 5, nw = (blockDim.x + 31) >> 5;
    v = wsum(v);
    if (lane == 0) sb[w] = v;
    __syncthreads();
    v = (threadIdx.x < nw) ? sb[threadIdx.x] : 0.f;
    if (w == 0) v = wsum(v);
    if (threadIdx.x == 0) sb[0] = v;
    __syncthreads();
    v = sb[0];
    __syncthreads();
    return v;
}
__device__ float bmax(float v, float* sb) {
    int lane = threadIdx.x & 31, w = threadIdx.x >> 5, nw = (blockDim.x + 31) >> 5;
    v = wmax(v);
    if (lane == 0) sb[w] = v;
    __syncthreads();
    v = (threadIdx.x < nw) ? sb[threadIdx.x] : -INFINITY;
    if (w == 0) v = wmax(v);
    if (threadIdx.x == 0) sb[0] = v;
    __syncthreads();
    v = sb[0];
    __syncthreads();
    return v;
}

// ---------- small kernels ----------
__global__ void k_cvt(const float* __restrict__ in, __nv_bfloat16* __restrict__ o, int n4) {
    int i = blockIdx.x * blockDim.x + threadIdx.x;
    if (i >= n4) return;
    float4 v = ((const float4*)in)[i];
    uint2 p;
    p.x = pkbf(v.x, v.y);
    p.y = pkbf(v.z, v.w);
    *(uint2*)(o + (size_t)i * 4) = p;
}

// transpose Wq (z=0) / Wk (z=1) -> fp32 + bf16; also zero g_Mt
__global__ void k_transp2(const float* __restrict__ Wq, const float* __restrict__ Wk, int D) {
    __shared__ float t[32][33];
    const float* in = blockIdx.z ? Wk : Wq;
    float* outp = blockIdx.z ? g_WkT : g_WqT;
    __nv_bfloat16* outb = blockIdx.z ? g_WkTB : g_WqTB;
    int x0 = blockIdx.x * 32, y0 = blockIdx.y * 32;
    int tx = threadIdx.x, ty = threadIdx.y;
    int tid = ty * 32 + tx;
    int bid = blockIdx.x + 32 * (blockIdx.y + 32 * blockIdx.z);
    if (tid < 128)
        ((float4*)g_Mt)[(size_t)bid * 128 + tid] = make_float4(0.f, 0.f, 0.f, 0.f);
    #pragma unroll
    for (int j = 0; j < 32; j += 8)
        t[ty + j][tx] = in[(size_t)(y0 + ty + j) * D + x0 + tx];
    __syncthreads();
    #pragma unroll
    for (int j = 0; j < 32; j += 8) {
        float v = t[tx][ty + j];
        size_t idx = (size_t)(x0 + ty + j) * D + y0 + tx;
        outp[idx] = v;
        outb[idx] = __float2bfloat16(v);
    }
}

// c1[e], c2[e]; block 0: c3; blocks 0..B-1: steps[b]
__global__ void k_cvecR(const float* __restrict__ bq, const float* __restrict__ bk,
                        const float* __restrict__ ms, const float* __restrict__ mt,
                        int D, int B, int S, int T) {
    int e = blockIdx.x;
    __shared__ float sb[32];
    const float4* r1 = (const float4*)(g_WqT + (size_t)e * D);
    const float4* r2 = (const float4*)(g_WkT + (size_t)e * D);
    float s1 = 0.f, s2 = 0.f, s3 = 0.f;
    for (int i = threadIdx.x; i < D / 4; i += blockDim.x) {
        float4 a = r1[i], c = *(const float4*)(bk + i * 4);
        s1 += a.x * c.x + a.y * c.y + a.z * c.z + a.w * c.w;
        float4 b2 = r2[i], d2 = *(const float4*)(bq + i * 4);
        s2 += b2.x * d2.x + b2.y * d2.y + b2.z * d2.z + b2.w * d2.w;
        if (e == 0) s3 += d2.x * c.x + d2.y * c.y + d2.z * c.z + d2.w * c.w;
    }
    s1 = bsum(s1, sb);
    s2 = bsum(s2, sb);
    if (e == 0) {
        s3 = bsum(s3, sb);
        if (threadIdx.x == 0) g_c3[0] = s3;
    }
    if (threadIdx.x == 0) { g_c1[e] = s1; g_c2[e] = s2; }
    if (e < B) {
        float ssum = 0.f;
        for (int i = threadIdx.x; i < S; i += blockDim.x) ssum += ms[(size_t)e * S + i];
        ssum = bsum(ssum, sb);
        float tsum = 0.f;
        for (int i = threadIdx.x; i < T; i += blockDim.x) tsum += mt[(size_t)e * T + i];
        tsum = bsum(tsum, sb);
        if (threadIdx.x == 0) g_steps[e] = ssum / tsum;
    }
}

__global__ void k_bskey(const float* __restrict__ key, int D) {
    int r = blockIdx.x;
    __shared__ float sb[32];
    float s = 0.f;
    const float4* kr = (const float4*)(key + (size_t)r * D);
    uint2* ob = (uint2*)(g_keyB + (size_t)r * D);
    for (int i = threadIdx.x; i < D / 4; i += blockDim.x) {
        float4 kv = kr[i], cv = *(const float4*)(g_c2 + i * 4);
        s += kv.x * cv.x + kv.y * cv.y + kv.z * cv.z + kv.w * cv.w;
        uint2 p;
        p.x = pkbf(kv.x, kv.y);
        p.y = pkbf(kv.z, kv.w);
        ob[i] = p;
    }
    s = bsum(s, sb);
    if (threadIdx.x == 0) g_bs[r] = s;
}

// ---------- windowed query = l_att @ key, fused gates/at ----------
#define QT 16
__global__ __launch_bounds__(256) void k_query(const float* __restrict__ mask_src,
                                               const float* __restrict__ key,
                                               const float* __restrict__ wg,
                                               const float* __restrict__ bg,
                                               int B, int T, int S, int D) {
    __shared__ float wk[QT][64];
    __shared__ float s_c[QT], s_m[QT], s_inv[QT];
    __shared__ int s_s0[QT], s_s1[QT], sh_lo, sh_hi;
    __shared__ float red1[QT], red2[QT];
    int b = blockIdx.y, t0 = blockIdx.x * QT, tid = threadIdx.x;
    int lane = tid & 31;
    float step = g_steps[b];
    if (tid < QT) {
        red1[tid] = 0.f; red2[tid] = 0.f;
        int t = t0 + tid;
        if (t < T) {
            float c = step * (float)t;
            int ci = (int)lrintf(c);
            ci = min(max(ci, 0), S - 1);
            int a0 = max(0, ci - 16), a1 = min(S - 1, ci + 16);
            float mx = -INFINITY;
            for (int s = a0; s <= a1; s++) {
                float d = (float)s - c;
                mx = fmaxf(mx, -(d * d) / 0.3f - INF_ * (1.0f - mask_src[(size_t)b * S + s]));
            }
            float sum = 0.f;
            for (int s = a0; s <= a1; s++) {
                float d = (float)s - c;
                sum += __expf(-(d * d) / 0.3f - INF_ * (1.0f - mask_src[(size_t)b * S + s]) - mx);
            }
            s_c[tid] = c; s_m[tid] = mx; s_inv[tid] = 1.0f / sum;
            s_s0[tid] = a0; s_s1[tid] = a1;
        } else {
            s_c[tid] = 0.f; s_m[tid] = 0.f; s_inv[tid] = 0.f;
            s_s0[tid] = 1; s_s1[tid] = 0;
        }
    }
    __syncthreads();
    if (tid == 0) {
        int lo = s_s0[0], hi = s_s1[0];
        for (int i = 1; i < QT; i++)
            if (s_s1[i] >= s_s0[i]) { lo = min(lo, s_s0[i]); hi = max(hi, s_s1[i]); }
        sh_lo = lo; sh_hi = hi;
    }
    __syncthreads();
    int lo = sh_lo, hi = sh_hi;
    float4 acc[QT];
    #pragma unroll
    for (int r = 0; r < QT; r++) acc[r] = make_float4(0.f, 0.f, 0.f, 0.f);
    for (int c0 = lo; c0 <= hi; c0 += 64) {
        int cnt = min(64, hi - c0 + 1);
        __syncthreads();
        for (int i = tid; i < QT * 64; i += 256) {
            int tr = i >> 6, j = i & 63, s = c0 + j;
            float w = 0.f;
            if (j < cnt && s >= s_s0[tr] && s <= s_s1[tr]) {
                float d = (float)s - s_c[tr];
                w = __expf(-(d * d) / 0.3f - INF_ * (1.0f - mask_src[(size_t)b * S + s]) - s_m[tr]) * s_inv[tr];
            }
            wk[tr][j] = w;
        }
        __syncthreads();
        for (int j = 0; j < cnt; j++) {
            float4 kv = *(const float4*)(key + ((size_t)b * S + c0 + j) * D + tid * 4);
            #pragma unroll
            for (int r = 0; r < QT; r++) {
                float w = wk[r][j];
                acc[r].x = fmaf(w, kv.x, acc[r].x);
                acc[r].y = fmaf(w, kv.y, acc[r].y);
                acc[r].z = fmaf(w, kv.z, acc[r].z);
                acc[r].w = fmaf(w, kv.w, acc[r].w);
            }
        }
        __syncthreads();
    }
    float4 wgv = *(const float4*)(wg + tid * 4);
    float4 c1v = *(const float4*)(g_c1 + tid * 4);
    #pragma unroll
    for (int r = 0; r < QT; r++) {
        int t = t0 + r;
        if (t < T) {
            size_t base = ((size_t)b * T + t) * D + tid * 4;
            uint2 p;
            p.x = pkbf(acc[r].x, acc[r].y);
            p.y = pkbf(acc[r].z, acc[r].w);
            *(uint2*)(g_queryB + base) = p;
        }
        float p1 = acc[r].x * wgv.x + acc[r].y * wgv.y + acc[r].z * wgv.z + acc[r].w * wgv.w;
        float p2 = acc[r].x * c1v.x + acc[r].y * c1v.y + acc[r].z * c1v.z + acc[r].w * c1v.w;
        p1 = wsum(p1);
        p2 = wsum(p2);
        if (lane == 0) { atomicAdd(&red1[r], p1); atomicAdd(&red2[r], p2); }
    }
    __syncthreads();
    if (tid < QT) {
        int t = t0 + tid;
        if (t < T) {
            g_gates[(size_t)b * T + t] = 1.0f / (1.0f + __expf(-(red1[tid] + bg[0])));
            g_at[(size_t)b * T + t] = red2[tid];
        }
    }
}

// ---------- mma wrappers ----------
__device__ __forceinline__ void mma_bf16(float* c, const uint32_t* a, const uint32_t* b) {
    asm volatile("mma.sync.aligned.m16n8k16.row.col.f32.bf16.bf16.f32 "
                 "{%0,%1,%2,%3},{%4,%5,%6,%7},{%8,%9},{%0,%1,%2,%3};"
                 : "+f"(c[0]), "+f"(c[1]), "+f"(c[2]), "+f"(c[3])
                 : "r"(a[0]), "r"(a[1]), "r"(a[2]), "r"(a[3]), "r"(b[0]), "r"(b[1]));
}
__device__ __forceinline__ void cpa16(uint32_t saddr, const void* g) {
    asm volatile("cp.async.cg.shared.global [%0], [%1], 16;" :: "r"(saddr), "l"(g));
}
__device__ __forceinline__ void ldsm4(uint32_t* r, uint32_t addr) {
    asm volatile("ldmatrix.sync.aligned.m8n8.x4.shared.b16 {%0,%1,%2,%3}, [%4];"
                 : "=r"(r[0]), "=r"(r[1]), "=r"(r[2]), "=r"(r[3]) : "r"(addr));
}

// ---------- bf16 NT GEMM (R10 config): 128x128 CTA, 8 warps of 64x32, 4-stage, K-chunk 32 ----------
// outmode: 0 = fp32 store, 1 = bf16 store, 2 = fp32 atomicAdd (split-K)
#define BQ 40
#define STG 4
#define SPITCH (128 * BQ)
#define GEMM_SMEM (STG * SPITCH * 2 * 2)
__global__ __launch_bounds__(256, 2) void k_bfgemm(
    const __nv_bfloat16* __restrict__ A, const __nv_bfloat16* __restrict__ B, void* __restrict__ Cout,
    int K, int lda, int ldb, int ldc,
    long long Abat, long long Bbat, long long Cbat, int outmode,
    const float* __restrict__ rowadd, int rowbat,
    const float* __restrict__ coladd, int colbat,
    const float* __restrict__ scalaradd)
{
    extern __shared__ __align__(16) __nv_bfloat16 dsm[];
    __nv_bfloat16* Asb = dsm;
    __nv_bfloat16* Bsb = dsm + STG * SPITCH;
    int tid = threadIdx.x, lane = tid & 31, wid = tid >> 5;
    int bz = blockIdx.z;
    A += Abat * bz; B += Bbat * bz;
    int m0 = blockIdx.y * 128, n0 = blockIdx.x * 128;
    int wm = (wid & 1) * 64, wn = (wid >> 1) * 32;
    float acc[4][4][4] = {};
    int lrow = tid >> 1, lcol = (tid & 1) * 16;
    const __nv_bfloat16* agp = A + (size_t)(m0 + lrow) * lda + lcol;
    const __nv_bfloat16* bgp = B + (size_t)(n0 + lrow) * ldb + lcol;
    int nk = K >> 5;
    int soff = lrow * BQ + lcol;
    #define LTB(kt, st) do { int _k = (kt) * 32; int _o = (st) * SPITCH + soff; \
        cpa16((uint32_t)__cvta_generic_to_shared(Asb + _o), agp + _k); \
        cpa16((uint32_t)__cvta_generic_to_shared(Asb + _o + 8), agp + _k + 8); \
        cpa16((uint32_t)__cvta_generic_to_shared(Bsb + _o), bgp + _k); \
        cpa16((uint32_t)__cvta_generic_to_shared(Bsb + _o + 8), bgp + _k + 8); \
    } while (0)

    #pragma unroll
    for (int i = 0; i < STG - 1; i++) {
        if (i < nk) LTB(i, i);
        asm volatile("cp.async.commit_group;");
    }
    int arow = (lane & 15), aoffb = (lane >> 4) * 8;
    int gq = lane >> 3;
    int brow = (gq >> 1) * 8 + (lane & 7), boffb = (gq & 1) * 8;
    for (int kt = 0; kt < nk; kt++) {
        int st = kt & (STG - 1);
        asm volatile("cp.async.wait_group %0;" :: "n"(STG - 2));
        __syncthreads();
        if (kt + STG - 1 < nk) LTB(kt + STG - 1, (kt + STG - 1) & (STG - 1));
        asm volatile("cp.async.commit_group;");
        const __nv_bfloat16* Ast = Asb + st * SPITCH;
        const __nv_bfloat16* Bst = Bsb + st * SPITCH;
        #pragma unroll
        for (int kk = 0; kk < 32; kk += 16) {
            uint32_t ar[4][4], br[4][2];
            #pragma unroll
            for (int mi = 0; mi < 4; mi++)
                ldsm4(ar[mi], (uint32_t)__cvta_generic_to_shared(
                    Ast + (wm + mi * 16 + arow) * BQ + kk + aoffb));
            #pragma unroll
            for (int nj = 0; nj < 2; nj++) {
                uint32_t t4[4];
                ldsm4(t4, (uint32_t)__cvta_generic_to_shared(
                    Bst + (wn + nj * 16 + brow) * BQ + kk + boffb));
                br[nj * 2][0] = t4[0];
                br[nj * 2][1] = t4[1];
                br[nj * 2 + 1][0] = t4[2];
                br[nj * 2 + 1][1] = t4[3];
            }
            #pragma unroll
            for (int mi = 0; mi < 4; mi++)
                #pragma unroll
                for (int ni = 0; ni < 4; ni++)
                    mma_bf16(acc[mi][ni], ar[mi], br[ni]);
        }
    }
    float sc = scalaradd ? scalaradd[0] : 0.f;
    #pragma unroll
    for (int mi = 0; mi < 4; mi++) {
        int r0 = m0 + wm + mi * 16 + (lane >> 2);
        float ra0 = sc + (rowadd ? rowadd[(size_t)rowbat * bz + r0] : 0.f);
        float ra1 = sc + (rowadd ? rowadd[(size_t)rowbat * bz + r0 + 8] : 0.f);
        #pragma unroll
        for (int ni = 0; ni < 4; ni++) {
            int c0 = n0 + wn + ni * 8 + (lane & 3) * 2;
            float cb0 = coladd ? coladd[(size_t)colbat * bz + c0] : 0.f;
            float cb1 = coladd ? coladd[(size_t)colbat * bz + c0 + 1] : 0.f;
            float v00 = acc[mi][ni][0] + ra0 + cb0, v01 = acc[mi][ni][1] + ra0 + cb1;
            float v10 = acc[mi][ni][2] + ra1 + cb0, v11 = acc[mi][ni][3] + ra1 + cb1;
            if (outmode == 1) {
                __nv_bfloat16* Cb = (__nv_bfloat16*)Cout + Cbat * bz;
                *(uint32_t*)(Cb + (size_t)r0 * ldc + c0) = pkbf(v00, v01);
                *(uint32_t*)(Cb + (size_t)(r0 + 8) * ldc + c0) = pkbf(v10, v11);
            } else if (outmode == 0) {
                float* Cf = (float*)Cout + Cbat * bz;
                *(float2*)(Cf + (size_t)r0 * ldc + c0) = make_float2(v00, v01);
                *(float2*)(Cf + (size_t)(r0 + 8) * ldc + c0) = make_float2(v10, v11);
            } else {
                float* Cf = (float*)Cout;
                atomicAdd(Cf + (size_t)r0 * ldc + c0, v00);
                atomicAdd(Cf + (size_t)r0 * ldc + c0 + 1, v01);
                atomicAdd(Cf + (size_t)(r0 + 8) * ldc + c0, v10);
                atomicAdd(Cf + (size_t)(r0 + 8) * ldc + c0 + 1, v11);
            }
        }
    }
}

// ---------- final: QK softmax over full row + windowed analytic l_att mixture ----------
__global__ void k_final(const float* __restrict__ mask_src, float* __restrict__ out,
                        const float* __restrict__ dots, int B, int T, int S, float invscale) {
    int bt = blockIdx.x;
    int b = bt / T, t = bt - b * T;
    extern __shared__ float sp[];   // S floats
    __shared__ float sred[32];
    __shared__ float sh_lmax, sh_linv;
    __shared__ int sh_a0, sh_a1;
    float c = g_steps[b] * (float)t;

    // warp 0: window softmax params for l_att (non-window terms underflow to exact 0)
    if (threadIdx.x < 32) {
        int ci = min(max((int)lrintf(c), 0), S - 1);
        int a0 = max(0, ci - 16), a1 = min(S - 1, ci + 16);
        float mx = -INFINITY, e = 0.f;
        float lg0 = -INFINITY, lg1 = -INFINITY;
        int s0 = a0 + (int)threadIdx.x;
        int s1 = s0 + 32;
        if (s0 <= a1) {
            float d = (float)s0 - c;
            lg0 = -(d * d) / 0.3f - INF_ * (1.0f - mask_src[(size_t)b * S + s0]);
        }
        if (s1 <= a1) {
            float d = (float)s1 - c;
            lg1 = -(d * d) / 0.3f - INF_ * (1.0f - mask_src[(size_t)b * S + s1]);
        }
        mx = wmax(fmaxf(lg0, lg1));
        if (s0 <= a1) e += __expf(lg0 - mx);
        if (s1 <= a1) e += __expf(lg1 - mx);
        e = wsum(e);
        if (threadIdx.x == 0) {
            sh_lmax = mx; sh_linv = 1.0f / e; sh_a0 = a0; sh_a1 = a1;
        }
    }

    float qmax = -INFINITY;
    for (int s = threadIdx.x; s < S; s += blockDim.x) {
        float msk = 1.0f - mask_src[(size_t)b * S + s];
        float x = (dots[(size_t)bt * S + s] - msk * INF_) * invscale;
        sp[s] = x;
        qmax = fmaxf(qmax, x);
    }
    qmax = bmax(qmax, sred);
    float qsum = 0.f;
    for (int s = threadIdx.x; s < S; s += blockDim.x) {
        float e = __expf(sp[s] - qmax);
        sp[s] = e;
        qsum += e;
    }
    qsum = bsum(qsum, sred);
    float qinv = 1.0f / qsum;
    float g = g_gates[bt];
    float omg = 1.0f - g;
    int a0 = sh_a0, a1 = sh_a1;
    float lmax = sh_lmax, linv = sh_linv;
    for (int s = threadIdx.x; s < S; s += blockDim.x) {
        float v = omg * sp[s] * qinv;
        if (s >= a0 && s <= a1) {
            float d = (float)s - c;
            float lg = -(d * d) / 0.3f - INF_ * (1.0f - mask_src[(size_t)b * S + s]);
            v += g * __expf(lg - lmax) * linv;
        }
        out[(size_t)bt * S + s] = v;
    }
}

// ---------- launch ----------
extern "C" void kernel_launch(void* const* d_in, const int* in_sizes, int n_in,
                              void* d_out, int out_size) {
    const float* key      = (const float*)d_in[0];
    const float* mask_src = (const float*)d_in[1];
    const float* mask_trg = (const float*)d_in[2];
    const float* Wq       = (const float*)d_in[3];
    const float* bq       = (const float*)d_in[4];
    const float* Wk       = (const float*)d_in[5];
    const float* bk       = (const float*)d_in[6];
    const float* wg       = (const float*)d_in[7];
    const float* bg       = (const float*)d_in[8];
    float* out = (float*)d_out;

    int D  = in_sizes[4];
    int BT = in_sizes[2];
    int S  = out_size / BT;
    int B  = in_sizes[1] / S;
    int T  = BT / B;

    float *p_Mt, *p_c3, *p_at, *p_bs, *p_dots;
    __nv_bfloat16 *p_keyB, *p_queryB, *p_qmB, *p_MtB, *p_WqTB, *p_WkTB;
    cudaGetSymbolAddress((void**)&p_Mt,    g_Mt);
    cudaGetSymbolAddress((void**)&p_c3,    g_c3);
    cudaGetSymbolAddress((void**)&p_at,    g_at);
    cudaGetSymbolAddress((void**)&p_bs,    g_bs);
    cudaGetSymbolAddress((void**)&p_dots,  g_dots);
    cudaGetSymbolAddress((void**)&p_keyB,  g_keyB);
    cudaGetSymbolAddress((void**)&p_queryB, g_queryB);
    cudaGetSymbolAddress((void**)&p_qmB,   g_qmB);
    cudaGetSymbolAddress((void**)&p_MtB,   g_MtB);
    cudaGetSymbolAddress((void**)&p_WqTB,  g_WqTB);
    cudaGetSymbolAddress((void**)&p_WkTB,  g_WkTB);

    cudaFuncSetAttribute(k_bfgemm, cudaFuncAttributeMaxDynamicSharedMemorySize, GEMM_SMEM);

    // 1: transpose Wq/Wk (+ zero Mt)
    {
        dim3 tb(32, 8);
        dim3 g(D / 32, D / 32, 2);
        k_transp2<<<g, tb>>>(Wq, Wk, D);
    }
    // 2: c1/c2/c3 + steps
    k_cvecR<<<D, 128>>>(bq, bk, mask_src, mask_trg, D, B, S, T);
    // 3: windowed query + gates/at
    {
        dim3 g((T + QT - 1) / QT, B);
        k_query<<<g, 256>>>(mask_src, key, wg, bg, B, T, S, D);
    }
    // 4: Mt split-K x4 (fp32 atomic accumulate)
    {
        dim3 g(D / 128, D / 128, 4);
        k_bfgemm<<<g, 256, GEMM_SMEM>>>(p_WkTB, p_WqTB, p_Mt, D / 4, D, D, D,
                                        D / 4, D / 4, 0, 2, nullptr, 0, nullptr, 0, nullptr);
    }
    // 5: Mt -> bf16
    k_cvt<<<(D * D / 4 + 255) / 256, 256>>>(p_Mt, p_MtB, D * D / 4);
    // 6 (ncu capture): qmB = queryB @ MtB^T
    {
        dim3 g(D / 128, BT / 128, 1);
        k_bfgemm<<<g, 256, GEMM_SMEM>>>(p_queryB, p_MtB, p_qmB, D, D, D, D,
                                        0, 0, 0, 1, nullptr, 0, nullptr, 0, nullptr);
    }
    // 7
    k_bskey<<<B * S, 128>>>(key, D);
    // 8: dots = qmB @ keyB^T + at + bs + c3
    {
        dim3 g(S / 128, T / 128, B);
        k_bfgemm<<<g, 256, GEMM_SMEM>>>(p_qmB, p_keyB, p_dots, D, D, D, S,
                                        (long long)T * D, (long long)S * D, (long long)T * S, 0,
                                        p_at, T, p_bs, S, p_c3);
    }
    // 9
    k_final<<<B * T, 256, S * (int)sizeof(float)>>>(mask_src, out, p_dots, B, T, S,
                                                    1.0f / sqrtf((float)D));
}

// round 14
// speedup vs baseline: 1.2636x; 1.0466x over previous
#include <cuda_runtime.h>
#include <cuda_bf16.h>
#include <stdint.h>
#include <math.h>

#define INF_ 1e10f

__device__ float g_dots [8388608];
__device__ float g_Mt   [1048576];
__device__ float g_WqT  [1048576];
__device__ float g_WkT  [1048576];
__device__ float g_c2   [1024];
__device__ float g_steps[64];
__device__ float g_bs   [8192];
__device__ float g_gates[8192];
__device__ __nv_bfloat16 g_keyB  [8388608];
__device__ __nv_bfloat16 g_queryB[8388608];
__device__ __nv_bfloat16 g_qmB   [8388608];
__device__ __nv_bfloat16 g_MtB   [1048576];
__device__ __nv_bfloat16 g_WqTB  [1048576];
__device__ __nv_bfloat16 g_WkTB  [1048576];

// ---------- helpers ----------
__device__ __forceinline__ uint32_t pkbf(float a, float b) {
    __nv_bfloat162 t = __halves2bfloat162(__float2bfloat16(a), __float2bfloat16(b));
    return *reinterpret_cast<uint32_t*>(&t);
}
__device__ __forceinline__ float wsum(float v) {
    #pragma unroll
    for (int o = 16; o; o >>= 1) v += __shfl_xor_sync(0xffffffffu, v, o);
    return v;
}
__device__ __forceinline__ float wmax(float v) {
    #pragma unroll
    for (int o = 16; o; o >>= 1) v = fmaxf(v, __shfl_xor_sync(0xffffffffu, v, o));
    return v;
}
__device__ float bsum(float v, float* sb) {
    int lane = threadIdx.x & 31, w = threadIdx.x >> 5, nw = (blockDim.x + 31) >> 5;
    v = wsum(v);
    if (lane == 0) sb[w] = v;
    __syncthreads();
    v = (threadIdx.x < nw) ? sb[threadIdx.x] : 0.f;
    if (w == 0) v = wsum(v);
    if (threadIdx.x == 0) sb[0] = v;
    __syncthreads();
    v = sb[0];
    __syncthreads();
    return v;
}
__device__ float bmax(float v, float* sb) {
    int lane = threadIdx.x & 31, w = threadIdx.x >> 5, nw = (blockDim.x + 31) >> 5;
    v = wmax(v);
    if (lane == 0) sb[w] = v;
    __syncthreads();
    v = (threadIdx.x < nw) ? sb[threadIdx.x] : -INFINITY;
    if (w == 0) v = wmax(v);
    if (threadIdx.x == 0) sb[0] = v;
    __syncthreads();
    v = sb[0];
    __syncthreads();
    return v;
}

// ---------- small kernels ----------
__global__ void k_cvt(const float* __restrict__ in, __nv_bfloat16* __restrict__ o, int n4) {
    int i = blockIdx.x * blockDim.x + threadIdx.x;
    if (i >= n4) return;
    float4 v = ((const float4*)in)[i];
    uint2 p;
    p.x = pkbf(v.x, v.y);
    p.y = pkbf(v.z, v.w);
    *(uint2*)(o + (size_t)i * 4) = p;
}

// transpose Wq (z=0) / Wk (z=1) -> fp32 + bf16; also zero g_Mt
__global__ void k_transp2(const float* __restrict__ Wq, const float* __restrict__ Wk, int D) {
    __shared__ float t[32][33];
    const float* in = blockIdx.z ? Wk : Wq;
    float* outp = blockIdx.z ? g_WkT : g_WqT;
    __nv_bfloat16* outb = blockIdx.z ? g_WkTB : g_WqTB;
    int x0 = blockIdx.x * 32, y0 = blockIdx.y * 32;
    int tx = threadIdx.x, ty = threadIdx.y;
    int tid = ty * 32 + tx;
    int bid = blockIdx.x + 32 * (blockIdx.y + 32 * blockIdx.z);
    if (tid < 128)
        ((float4*)g_Mt)[(size_t)bid * 128 + tid] = make_float4(0.f, 0.f, 0.f, 0.f);
    #pragma unroll
    for (int j = 0; j < 32; j += 8)
        t[ty + j][tx] = in[(size_t)(y0 + ty + j) * D + x0 + tx];
    __syncthreads();
    #pragma unroll
    for (int j = 0; j < 32; j += 8) {
        float v = t[tx][ty + j];
        size_t idx = (size_t)(x0 + ty + j) * D + y0 + tx;
        outp[idx] = v;
        outb[idx] = __float2bfloat16(v);
    }
}

// c2[e] = dot(WkT[e,:], bq); blocks 0..B-1 also: steps[b]
__global__ void k_cvecR(const float* __restrict__ bq,
                        const float* __restrict__ ms, const float* __restrict__ mt,
                        int D, int B, int S, int T) {
    int e = blockIdx.x;
    __shared__ float sb[32];
    const float4* r2 = (const float4*)(g_WkT + (size_t)e * D);
    float s2 = 0.f;
    for (int i = threadIdx.x; i < D / 4; i += blockDim.x) {
        float4 b2 = r2[i], d2 = *(const float4*)(bq + i * 4);
        s2 += b2.x * d2.x + b2.y * d2.y + b2.z * d2.z + b2.w * d2.w;
    }
    s2 = bsum(s2, sb);
    if (threadIdx.x == 0) g_c2[e] = s2;
    if (e < B) {
        float ssum = 0.f;
        for (int i = threadIdx.x; i < S; i += blockDim.x) ssum += ms[(size_t)e * S + i];
        ssum = bsum(ssum, sb);
        float tsum = 0.f;
        for (int i = threadIdx.x; i < T; i += blockDim.x) tsum += mt[(size_t)e * T + i];
        tsum = bsum(tsum, sb);
        if (threadIdx.x == 0) g_steps[e] = ssum / tsum;
    }
}

__global__ void k_bskey(const float* __restrict__ key, int D) {
    int r = blockIdx.x;
    __shared__ float sb[32];
    float s = 0.f;
    const float4* kr = (const float4*)(key + (size_t)r * D);
    uint2* ob = (uint2*)(g_keyB + (size_t)r * D);
    for (int i = threadIdx.x; i < D / 4; i += blockDim.x) {
        float4 kv = kr[i], cv = *(const float4*)(g_c2 + i * 4);
        s += kv.x * cv.x + kv.y * cv.y + kv.z * cv.z + kv.w * cv.w;
        uint2 p;
        p.x = pkbf(kv.x, kv.y);
        p.y = pkbf(kv.z, kv.w);
        ob[i] = p;
    }
    s = bsum(s, sb);
    if (threadIdx.x == 0) g_bs[r] = s;
}

// ---------- windowed query = l_att @ key, fused gates ----------
#define QT 16
__global__ __launch_bounds__(256) void k_query(const float* __restrict__ mask_src,
                                               const float* __restrict__ key,
                                               const float* __restrict__ wg,
                                               const float* __restrict__ bg,
                                               int B, int T, int S, int D) {
    __shared__ float wk[QT][64];
    __shared__ float s_c[QT], s_m[QT], s_inv[QT];
    __shared__ int s_s0[QT], s_s1[QT], sh_lo, sh_hi;
    __shared__ float red1[QT];
    int b = blockIdx.y, t0 = blockIdx.x * QT, tid = threadIdx.x;
    int lane = tid & 31;
    float step = g_steps[b];
    if (tid < QT) {
        red1[tid] = 0.f;
        int t = t0 + tid;
        if (t < T) {
            float c = step * (float)t;
            int ci = (int)lrintf(c);
            ci = min(max(ci, 0), S - 1);
            int a0 = max(0, ci - 16), a1 = min(S - 1, ci + 16);
            float mx = -INFINITY;
            for (int s = a0; s <= a1; s++) {
                float d = (float)s - c;
                mx = fmaxf(mx, -(d * d) / 0.3f - INF_ * (1.0f - mask_src[(size_t)b * S + s]));
            }
            float sum = 0.f;
            for (int s = a0; s <= a1; s++) {
                float d = (float)s - c;
                sum += __expf(-(d * d) / 0.3f - INF_ * (1.0f - mask_src[(size_t)b * S + s]) - mx);
            }
            s_c[tid] = c; s_m[tid] = mx; s_inv[tid] = 1.0f / sum;
            s_s0[tid] = a0; s_s1[tid] = a1;
        } else {
            s_c[tid] = 0.f; s_m[tid] = 0.f; s_inv[tid] = 0.f;
            s_s0[tid] = 1; s_s1[tid] = 0;
        }
    }
    __syncthreads();
    if (tid == 0) {
        int lo = s_s0[0], hi = s_s1[0];
        for (int i = 1; i < QT; i++)
            if (s_s1[i] >= s_s0[i]) { lo = min(lo, s_s0[i]); hi = max(hi, s_s1[i]); }
        sh_lo = lo; sh_hi = hi;
    }
    __syncthreads();
    int lo = sh_lo, hi = sh_hi;
    float4 acc[QT];
    #pragma unroll
    for (int r = 0; r < QT; r++) acc[r] = make_float4(0.f, 0.f, 0.f, 0.f);
    for (int c0 = lo; c0 <= hi; c0 += 64) {
        int cnt = min(64, hi - c0 + 1);
        __syncthreads();
        for (int i = tid; i < QT * 64; i += 256) {
            int tr = i >> 6, j = i & 63, s = c0 + j;
            float w = 0.f;
            if (j < cnt && s >= s_s0[tr] && s <= s_s1[tr]) {
                float d = (float)s - s_c[tr];
                w = __expf(-(d * d) / 0.3f - INF_ * (1.0f - mask_src[(size_t)b * S + s]) - s_m[tr]) * s_inv[tr];
            }
            wk[tr][j] = w;
        }
        __syncthreads();
        for (int j = 0; j < cnt; j++) {
            float4 kv = *(const float4*)(key + ((size_t)b * S + c0 + j) * D + tid * 4);
            #pragma unroll
            for (int r = 0; r < QT; r++) {
                float w = wk[r][j];
                acc[r].x = fmaf(w, kv.x, acc[r].x);
                acc[r].y = fmaf(w, kv.y, acc[r].y);
                acc[r].z = fmaf(w, kv.z, acc[r].z);
                acc[r].w = fmaf(w, kv.w, acc[r].w);
            }
        }
        __syncthreads();
    }
    float4 wgv = *(const float4*)(wg + tid * 4);
    #pragma unroll
    for (int r = 0; r < QT; r++) {
        int t = t0 + r;
        if (t < T) {
            size_t base = ((size_t)b * T + t) * D + tid * 4;
            uint2 p;
            p.x = pkbf(acc[r].x, acc[r].y);
            p.y = pkbf(acc[r].z, acc[r].w);
            *(uint2*)(g_queryB + base) = p;
        }
        float p1 = acc[r].x * wgv.x + acc[r].y * wgv.y + acc[r].z * wgv.z + acc[r].w * wgv.w;
        p1 = wsum(p1);
        if (lane == 0) atomicAdd(&red1[r], p1);
    }
    __syncthreads();
    if (tid < QT) {
        int t = t0 + tid;
        if (t < T)
            g_gates[(size_t)b * T + t] = 1.0f / (1.0f + __expf(-(red1[tid] + bg[0])));
    }
}

// ---------- mma wrappers ----------
__device__ __forceinline__ void mma_bf16(float* c, const uint32_t* a, const uint32_t* b) {
    asm volatile("mma.sync.aligned.m16n8k16.row.col.f32.bf16.bf16.f32 "
                 "{%0,%1,%2,%3},{%4,%5,%6,%7},{%8,%9},{%0,%1,%2,%3};"
                 : "+f"(c[0]), "+f"(c[1]), "+f"(c[2]), "+f"(c[3])
                 : "r"(a[0]), "r"(a[1]), "r"(a[2]), "r"(a[3]), "r"(b[0]), "r"(b[1]));
}
__device__ __forceinline__ void cpa16(uint32_t saddr, const void* g) {
    asm volatile("cp.async.cg.shared.global [%0], [%1], 16;" :: "r"(saddr), "l"(g));
}
__device__ __forceinline__ void ldsm4(uint32_t* r, uint32_t addr) {
    asm volatile("ldmatrix.sync.aligned.m8n8.x4.shared.b16 {%0,%1,%2,%3}, [%4];"
                 : "=r"(r[0]), "=r"(r[1]), "=r"(r[2]), "=r"(r[3]) : "r"(addr));
}

// ---------- bf16 NT GEMM (R10 config): 128x128 CTA, 8 warps of 64x32, 4-stage, K-chunk 32 ----------
// outmode: 0 = fp32 store, 1 = bf16 store, 2 = fp32 atomicAdd (split-K)
#define BQ 40
#define STG 4
#define SPITCH (128 * BQ)
#define GEMM_SMEM (STG * SPITCH * 2 * 2)
__global__ __launch_bounds__(256, 2) void k_bfgemm(
    const __nv_bfloat16* __restrict__ A, const __nv_bfloat16* __restrict__ B, void* __restrict__ Cout,
    int K, int lda, int ldb, int ldc,
    long long Abat, long long Bbat, long long Cbat, int outmode,
    const float* __restrict__ coladd, int colbat)
{
    extern __shared__ __align__(16) __nv_bfloat16 dsm[];
    __nv_bfloat16* Asb = dsm;
    __nv_bfloat16* Bsb = dsm + STG * SPITCH;
    int tid = threadIdx.x, lane = tid & 31, wid = tid >> 5;
    int bz = blockIdx.z;
    A += Abat * bz; B += Bbat * bz;
    int m0 = blockIdx.y * 128, n0 = blockIdx.x * 128;
    int wm = (wid & 1) * 64, wn = (wid >> 1) * 32;
    float acc[4][4][4] = {};
    int lrow = tid >> 1, lcol = (tid & 1) * 16;
    const __nv_bfloat16* agp = A + (size_t)(m0 + lrow) * lda + lcol;
    const __nv_bfloat16* bgp = B + (size_t)(n0 + lrow) * ldb + lcol;
    int nk = K >> 5;
    int soff = lrow * BQ + lcol;
    #define LTB(kt, st) do { int _k = (kt) * 32; int _o = (st) * SPITCH + soff; \
        cpa16((uint32_t)__cvta_generic_to_shared(Asb + _o), agp + _k); \
        cpa16((uint32_t)__cvta_generic_to_shared(Asb + _o + 8), agp + _k + 8); \
        cpa16((uint32_t)__cvta_generic_to_shared(Bsb + _o), bgp + _k); \
        cpa16((uint32_t)__cvta_generic_to_shared(Bsb + _o + 8), bgp + _k + 8); \
    } while (0)

    #pragma unroll
    for (int i = 0; i < STG - 1; i++) {
        if (i < nk) LTB(i, i);
        asm volatile("cp.async.commit_group;");
    }
    int arow = (lane & 15), aoffb = (lane >> 4) * 8;
    int gq = lane >> 3;
    int brow = (gq >> 1) * 8 + (lane & 7), boffb = (gq & 1) * 8;
    for (int kt = 0; kt < nk; kt++) {
        int st = kt & (STG - 1);
        asm volatile("cp.async.wait_group %0;" :: "n"(STG - 2));
        __syncthreads();
        if (kt + STG - 1 < nk) LTB(kt + STG - 1, (kt + STG - 1) & (STG - 1));
        asm volatile("cp.async.commit_group;");
        const __nv_bfloat16* Ast = Asb + st * SPITCH;
        const __nv_bfloat16* Bst = Bsb + st * SPITCH;
        #pragma unroll
        for (int kk = 0; kk < 32; kk += 16) {
            uint32_t ar[4][4], br[4][2];
            #pragma unroll
            for (int mi = 0; mi < 4; mi++)
                ldsm4(ar[mi], (uint32_t)__cvta_generic_to_shared(
                    Ast + (wm + mi * 16 + arow) * BQ + kk + aoffb));
            #pragma unroll
            for (int nj = 0; nj < 2; nj++) {
                uint32_t t4[4];
                ldsm4(t4, (uint32_t)__cvta_generic_to_shared(
                    Bst + (wn + nj * 16 + brow) * BQ + kk + boffb));
                br[nj * 2][0] = t4[0];
                br[nj * 2][1] = t4[1];
                br[nj * 2 + 1][0] = t4[2];
                br[nj * 2 + 1][1] = t4[3];
            }
            #pragma unroll
            for (int mi = 0; mi < 4; mi++)
                #pragma unroll
                for (int ni = 0; ni < 4; ni++)
                    mma_bf16(acc[mi][ni], ar[mi], br[ni]);
        }
    }
    #pragma unroll
    for (int mi = 0; mi < 4; mi++) {
        int r0 = m0 + wm + mi * 16 + (lane >> 2);
        #pragma unroll
        for (int ni = 0; ni < 4; ni++) {
            int c0 = n0 + wn + ni * 8 + (lane & 3) * 2;
            float cb0 = coladd ? coladd[(size_t)colbat * bz + c0] : 0.f;
            float cb1 = coladd ? coladd[(size_t)colbat * bz + c0 + 1] : 0.f;
            float v00 = acc[mi][ni][0] + cb0, v01 = acc[mi][ni][1] + cb1;
            float v10 = acc[mi][ni][2] + cb0, v11 = acc[mi][ni][3] + cb1;
            if (outmode == 1) {
                __nv_bfloat16* Cb = (__nv_bfloat16*)Cout + Cbat * bz;
                *(uint32_t*)(Cb + (size_t)r0 * ldc + c0) = pkbf(v00, v01);
                *(uint32_t*)(Cb + (size_t)(r0 + 8) * ldc + c0) = pkbf(v10, v11);
            } else if (outmode == 0) {
                float* Cf = (float*)Cout + Cbat * bz;
                *(float2*)(Cf + (size_t)r0 * ldc + c0) = make_float2(v00, v01);
                *(float2*)(Cf + (size_t)(r0 + 8) * ldc + c0) = make_float2(v10, v11);
            } else {
                float* Cf = (float*)Cout;
                atomicAdd(Cf + (size_t)r0 * ldc + c0, v00);
                atomicAdd(Cf + (size_t)r0 * ldc + c0 + 1, v01);
                atomicAdd(Cf + (size_t)(r0 + 8) * ldc + c0, v10);
                atomicAdd(Cf + (size_t)(r0 + 8) * ldc + c0 + 1, v11);
            }
        }
    }
}

// ---------- final: register-resident QK softmax + windowed analytic l_att ----------
// requires S == 4 * blockDim.x
__global__ __launch_bounds__(256) void k_final(const float* __restrict__ mask_src,
                                               float* __restrict__ out,
                                               const float* __restrict__ dots,
                                               int B, int T, int S, float invscale) {
    int bt = blockIdx.x;
    int b = bt / T, t = bt - b * T;
    __shared__ float sred[32];
    __shared__ float sh_lmax, sh_linv;
    __shared__ int sh_a0, sh_a1;
    float c = g_steps[b] * (float)t;

    // warp 0: window softmax params for l_att (out-of-window terms underflow to exact 0)
    if (threadIdx.x < 32) {
        int ci = min(max((int)lrintf(c), 0), S - 1);
        int a0 = max(0, ci - 16), a1 = min(S - 1, ci + 16);
        float lg0 = -INFINITY, lg1 = -INFINITY;
        int s0 = a0 + (int)threadIdx.x;
        int s1 = s0 + 32;
        if (s0 <= a1) {
            float d = (float)s0 - c;
            lg0 = -(d * d) / 0.3f - INF_ * (1.0f - mask_src[(size_t)b * S + s0]);
        }
        if (s1 <= a1) {
            float d = (float)s1 - c;
            lg1 = -(d * d) / 0.3f - INF_ * (1.0f - mask_src[(size_t)b * S + s1]);
        }
        float mx = wmax(fmaxf(lg0, lg1));
        float e = 0.f;
        if (s0 <= a1) e += __expf(lg0 - mx);
        if (s1 <= a1) e += __expf(lg1 - mx);
        e = wsum(e);
        if (threadIdx.x == 0) {
            sh_lmax = mx; sh_linv = 1.0f / e; sh_a0 = a0; sh_a1 = a1;
        }
    }

    int i0 = threadIdx.x * 4;
    float4 mk = *(const float4*)(mask_src + (size_t)b * S + i0);
    float4 dv = *(const float4*)(dots + (size_t)bt * S + i0);
    float4 x;
    x.x = (dv.x - (1.0f - mk.x) * INF_) * invscale;
    x.y = (dv.y - (1.0f - mk.y) * INF_) * invscale;
    x.z = (dv.z - (1.0f - mk.z) * INF_) * invscale;
    x.w = (dv.w - (1.0f - mk.w) * INF_) * invscale;
    float qmax = fmaxf(fmaxf(x.x, x.y), fmaxf(x.z, x.w));
    qmax = bmax(qmax, sred);
    float4 e;
    e.x = __expf(x.x - qmax);
    e.y = __expf(x.y - qmax);
    e.z = __expf(x.z - qmax);
    e.w = __expf(x.w - qmax);
    float qsum = bsum(e.x + e.y + e.z + e.w, sred);
    float qinv = 1.0f / qsum;
    float g = g_gates[bt];
    float omg = 1.0f - g;
    int a0 = sh_a0, a1 = sh_a1;
    float lmax = sh_lmax, linv = sh_linv;
    float4 o;
    o.x = omg * e.x * qinv;
    o.y = omg * e.y * qinv;
    o.z = omg * e.z * qinv;
    o.w = omg * e.w * qinv;
    if (i0 + 3 >= a0 && i0 <= a1) {
        float mks[4] = {mk.x, mk.y, mk.z, mk.w};
        float* os = &o.x;
        #pragma unroll
        for (int j = 0; j < 4; j++) {
            int s = i0 + j;
            if (s >= a0 && s <= a1) {
                float d = (float)s - c;
                float lg = -(d * d) / 0.3f - INF_ * (1.0f - mks[j]);
                os[j] += g * __expf(lg - lmax) * linv;
            }
        }
    }
    *(float4*)(out + (size_t)bt * S + i0) = o;
}

// ---------- launch ----------
extern "C" void kernel_launch(void* const* d_in, const int* in_sizes, int n_in,
                              void* d_out, int out_size) {
    const float* key      = (const float*)d_in[0];
    const float* mask_src = (const float*)d_in[1];
    const float* mask_trg = (const float*)d_in[2];
    const float* Wq       = (const float*)d_in[3];
    const float* bq       = (const float*)d_in[4];
    const float* Wk       = (const float*)d_in[5];
    const float* bk       = (const float*)d_in[6];
    const float* wg       = (const float*)d_in[7];
    const float* bg       = (const float*)d_in[8];
    float* out = (float*)d_out;

    int D  = in_sizes[4];
    int BT = in_sizes[2];
    int S  = out_size / BT;
    int B  = in_sizes[1] / S;
    int T  = BT / B;

    float *p_Mt, *p_bs, *p_dots;
    __nv_bfloat16 *p_keyB, *p_queryB, *p_qmB, *p_MtB, *p_WqTB, *p_WkTB;
    cudaGetSymbolAddress((void**)&p_Mt,    g_Mt);
    cudaGetSymbolAddress((void**)&p_bs,    g_bs);
    cudaGetSymbolAddress((void**)&p_dots,  g_dots);
    cudaGetSymbolAddress((void**)&p_keyB,  g_keyB);
    cudaGetSymbolAddress((void**)&p_queryB, g_queryB);
    cudaGetSymbolAddress((void**)&p_qmB,   g_qmB);
    cudaGetSymbolAddress((void**)&p_MtB,   g_MtB);
    cudaGetSymbolAddress((void**)&p_WqTB,  g_WqTB);
    cudaGetSymbolAddress((void**)&p_WkTB,  g_WkTB);

    cudaFuncSetAttribute(k_bfgemm, cudaFuncAttributeMaxDynamicSharedMemorySize, GEMM_SMEM);

    // 1: transpose Wq/Wk (+ zero Mt)
    {
        dim3 tb(32, 8);
        dim3 g(D / 32, D / 32, 2);
        k_transp2<<<g, tb>>>(Wq, Wk, D);
    }
    // 2: c2 + steps
    k_cvecR<<<D, 128>>>(bq, mask_src, mask_trg, D, B, S, T);
    // 3: windowed query + gates
    {
        dim3 g((T + QT - 1) / QT, B);
        k_query<<<g, 256>>>(mask_src, key, wg, bg, B, T, S, D);
    }
    // 4: Mt split-K x4 (fp32 atomic accumulate)
    {
        dim3 g(D / 128, D / 128, 4);
        k_bfgemm<<<g, 256, GEMM_SMEM>>>(p_WkTB, p_WqTB, p_Mt, D / 4, D, D, D,
                                        D / 4, D / 4, 0, 2, nullptr, 0);
    }
    // 5: Mt -> bf16
    k_cvt<<<(D * D / 4 + 255) / 256, 256>>>(p_Mt, p_MtB, D * D / 4);
    // 6: qmB = queryB @ MtB^T
    {
        dim3 g(D / 128, BT / 128, 1);
        k_bfgemm<<<g, 256, GEMM_SMEM>>>(p_queryB, p_MtB, p_qmB, D, D, D, D,
                                        0, 0, 0, 1, nullptr, 0);
    }
    // 7
    k_bskey<<<B * S, 128>>>(key, D);
    // 8: dots = qmB @ keyB^T + bs
    {
        dim3 g(S / 128, T / 128, B);
        k_bfgemm<<<g, 256, GEMM_SMEM>>>(p_qmB, p_keyB, p_dots, D, D, D, S,
                                        (long long)T * D, (long long)S * D, (long long)T * S, 0,
                                        p_bs, S);
    }
    // 9
    k_final<<<B * T, S / 4>>>(mask_src, out, p_dots, B, T, S, 1.0f / sqrtf((float)D));
}

// round 15
// speedup vs baseline: 1.3634x; 1.0790x over previous
#include <cuda_runtime.h>
#include <cuda_bf16.h>
#include <stdint.h>
#include <math.h>

#define INF_ 1e10f

__device__ float g_dots [8388608];
__device__ float g_Mt   [1048576];
__device__ float g_WqT  [1048576];
__device__ float g_WkT  [1048576];
__device__ float g_c2   [1024];
__device__ float g_steps[64];
__device__ float g_bs   [8192];
__device__ float g_gates[8192];
__device__ __nv_bfloat16 g_keyB  [8388608];
__device__ __nv_bfloat16 g_queryB[8388608];
__device__ __nv_bfloat16 g_qmB   [8388608];
__device__ __nv_bfloat16 g_MtB   [1048576];
__device__ __nv_bfloat16 g_WqTB  [1048576];
__device__ __nv_bfloat16 g_WkTB  [1048576];

// ---------- helpers ----------
__device__ __forceinline__ uint32_t pkbf(float a, float b) {
    __nv_bfloat162 t = __halves2bfloat162(__float2bfloat16(a), __float2bfloat16(b));
    return *reinterpret_cast<uint32_t*>(&t);
}
__device__ __forceinline__ float wsum(float v) {
    #pragma unroll
    for (int o = 16; o; o >>= 1) v += __shfl_xor_sync(0xffffffffu, v, o);
    return v;
}
__device__ __forceinline__ float wmax(float v) {
    #pragma unroll
    for (int o = 16; o; o >>= 1) v = fmaxf(v, __shfl_xor_sync(0xffffffffu, v, o));
    return v;
}
__device__ float bsum(float v, float* sb) {
    int lane = threadIdx.x & 31, w = threadIdx.x >> 5, nw = (blockDim.x + 31) >> 5;
    v = wsum(v);
    if (lane == 0) sb[w] = v;
    __syncthreads();
    v = (threadIdx.x < nw) ? sb[threadIdx.x] : 0.f;
    if (w == 0) v = wsum(v);
    if (threadIdx.x == 0) sb[0] = v;
    __syncthreads();
    v = sb[0];
    __syncthreads();
    return v;
}
__device__ float bmax(float v, float* sb) {
    int lane = threadIdx.x & 31, w = threadIdx.x >> 5, nw = (blockDim.x + 31) >> 5;
    v = wmax(v);
    if (lane == 0) sb[w] = v;
    __syncthreads();
    v = (threadIdx.x < nw) ? sb[threadIdx.x] : -INFINITY;
    if (w == 0) v = wmax(v);
    if (threadIdx.x == 0) sb[0] = v;
    __syncthreads();
    v = sb[0];
    __syncthreads();
    return v;
}

// ---------- small kernels ----------
__global__ void k_cvt(const float* __restrict__ in, __nv_bfloat16* __restrict__ o, int n4) {
    int i = blockIdx.x * blockDim.x + threadIdx.x;
    if (i >= n4) return;
    float4 v = ((const float4*)in)[i];
    uint2 p;
    p.x = pkbf(v.x, v.y);
    p.y = pkbf(v.z, v.w);
    *(uint2*)(o + (size_t)i * 4) = p;
}

// transpose Wq (z=0) / Wk (z=1) -> fp32 + bf16; also zero g_Mt
__global__ void k_transp2(const float* __restrict__ Wq, const float* __restrict__ Wk, int D) {
    __shared__ float t[32][33];
    const float* in = blockIdx.z ? Wk : Wq;
    float* outp = blockIdx.z ? g_WkT : g_WqT;
    __nv_bfloat16* outb = blockIdx.z ? g_WkTB : g_WqTB;
    int x0 = blockIdx.x * 32, y0 = blockIdx.y * 32;
    int tx = threadIdx.x, ty = threadIdx.y;
    int tid = ty * 32 + tx;
    int bid = blockIdx.x + 32 * (blockIdx.y + 32 * blockIdx.z);
    if (tid < 128)
        ((float4*)g_Mt)[(size_t)bid * 128 + tid] = make_float4(0.f, 0.f, 0.f, 0.f);
    #pragma unroll
    for (int j = 0; j < 32; j += 8)
        t[ty + j][tx] = in[(size_t)(y0 + ty + j) * D + x0 + tx];
    __syncthreads();
    #pragma unroll
    for (int j = 0; j < 32; j += 8) {
        float v = t[tx][ty + j];
        size_t idx = (size_t)(x0 + ty + j) * D + y0 + tx;
        outp[idx] = v;
        outb[idx] = __float2bfloat16(v);
    }
}

// c2[e] = dot(WkT[e,:], bq); blocks 0..B-1 also: steps[b]
__global__ void k_cvecR(const float* __restrict__ bq,
                        const float* __restrict__ ms, const float* __restrict__ mt,
                        int D, int B, int S, int T) {
    int e = blockIdx.x;
    __shared__ float sb[32];
    const float4* r2 = (const float4*)(g_WkT + (size_t)e * D);
    float s2 = 0.f;
    for (int i = threadIdx.x; i < D / 4; i += blockDim.x) {
        float4 b2 = r2[i], d2 = *(const float4*)(bq + i * 4);
        s2 += b2.x * d2.x + b2.y * d2.y + b2.z * d2.z + b2.w * d2.w;
    }
    s2 = bsum(s2, sb);
    if (threadIdx.x == 0) g_c2[e] = s2;
    if (e < B) {
        float ssum = 0.f;
        for (int i = threadIdx.x; i < S; i += blockDim.x) ssum += ms[(size_t)e * S + i];
        ssum = bsum(ssum, sb);
        float tsum = 0.f;
        for (int i = threadIdx.x; i < T; i += blockDim.x) tsum += mt[(size_t)e * T + i];
        tsum = bsum(tsum, sb);
        if (threadIdx.x == 0) g_steps[e] = ssum / tsum;
    }
}

__global__ void k_bskey(const float* __restrict__ key, int D) {
    int r = blockIdx.x;
    __shared__ float sb[32];
    float s = 0.f;
    const float4* kr = (const float4*)(key + (size_t)r * D);
    uint2* ob = (uint2*)(g_keyB + (size_t)r * D);
    for (int i = threadIdx.x; i < D / 4; i += blockDim.x) {
        float4 kv = kr[i], cv = *(const float4*)(g_c2 + i * 4);
        s += kv.x * cv.x + kv.y * cv.y + kv.z * cv.z + kv.w * cv.w;
        uint2 p;
        p.x = pkbf(kv.x, kv.y);
        p.y = pkbf(kv.z, kv.w);
        ob[i] = p;
    }
    s = bsum(s, sb);
    if (threadIdx.x == 0) g_bs[r] = s;
}

// ---------- windowed query = l_att @ key, fused gates ----------
#define QT 16
__global__ __launch_bounds__(256) void k_query(const float* __restrict__ mask_src,
                                               const float* __restrict__ key,
                                               const float* __restrict__ wg,
                                               const float* __restrict__ bg,
                                               int B, int T, int S, int D) {
    __shared__ float wk[QT][64];
    __shared__ float s_c[QT], s_m[QT], s_inv[QT];
    __shared__ int s_s0[QT], s_s1[QT], sh_lo, sh_hi;
    __shared__ float red1[QT];
    int b = blockIdx.y, t0 = blockIdx.x * QT, tid = threadIdx.x;
    int lane = tid & 31;
    float step = g_steps[b];
    if (tid < QT) {
        red1[tid] = 0.f;
        int t = t0 + tid;
        if (t < T) {
            float c = step * (float)t;
            int ci = (int)lrintf(c);
            ci = min(max(ci, 0), S - 1);
            int a0 = max(0, ci - 16), a1 = min(S - 1, ci + 16);
            float mx = -INFINITY;
            for (int s = a0; s <= a1; s++) {
                float d = (float)s - c;
                mx = fmaxf(mx, -(d * d) / 0.3f - INF_ * (1.0f - mask_src[(size_t)b * S + s]));
            }
            float sum = 0.f;
            for (int s = a0; s <= a1; s++) {
                float d = (float)s - c;
                sum += __expf(-(d * d) / 0.3f - INF_ * (1.0f - mask_src[(size_t)b * S + s]) - mx);
            }
            s_c[tid] = c; s_m[tid] = mx; s_inv[tid] = 1.0f / sum;
            s_s0[tid] = a0; s_s1[tid] = a1;
        } else {
            s_c[tid] = 0.f; s_m[tid] = 0.f; s_inv[tid] = 0.f;
            s_s0[tid] = 1; s_s1[tid] = 0;
        }
    }
    __syncthreads();
    if (tid == 0) {
        int lo = s_s0[0], hi = s_s1[0];
        for (int i = 1; i < QT; i++)
            if (s_s1[i] >= s_s0[i]) { lo = min(lo, s_s0[i]); hi = max(hi, s_s1[i]); }
        sh_lo = lo; sh_hi = hi;
    }
    __syncthreads();
    int lo = sh_lo, hi = sh_hi;
    float4 acc[QT];
    #pragma unroll
    for (int r = 0; r < QT; r++) acc[r] = make_float4(0.f, 0.f, 0.f, 0.f);
    for (int c0 = lo; c0 <= hi; c0 += 64) {
        int cnt = min(64, hi - c0 + 1);
        __syncthreads();
        for (int i = tid; i < QT * 64; i += 256) {
            int tr = i >> 6, j = i & 63, s = c0 + j;
            float w = 0.f;
            if (j < cnt && s >= s_s0[tr] && s <= s_s1[tr]) {
                float d = (float)s - s_c[tr];
                w = __expf(-(d * d) / 0.3f - INF_ * (1.0f - mask_src[(size_t)b * S + s]) - s_m[tr]) * s_inv[tr];
            }
            wk[tr][j] = w;
        }
        __syncthreads();
        for (int j = 0; j < cnt; j++) {
            float4 kv = *(const float4*)(key + ((size_t)b * S + c0 + j) * D + tid * 4);
            #pragma unroll
            for (int r = 0; r < QT; r++) {
                float w = wk[r][j];
                acc[r].x = fmaf(w, kv.x, acc[r].x);
                acc[r].y = fmaf(w, kv.y, acc[r].y);
                acc[r].z = fmaf(w, kv.z, acc[r].z);
                acc[r].w = fmaf(w, kv.w, acc[r].w);
            }
        }
        __syncthreads();
    }
    float4 wgv = *(const float4*)(wg + tid * 4);
    #pragma unroll
    for (int r = 0; r < QT; r++) {
        int t = t0 + r;
        if (t < T) {
            size_t base = ((size_t)b * T + t) * D + tid * 4;
            uint2 p;
            p.x = pkbf(acc[r].x, acc[r].y);
            p.y = pkbf(acc[r].z, acc[r].w);
            *(uint2*)(g_queryB + base) = p;
        }
        float p1 = acc[r].x * wgv.x + acc[r].y * wgv.y + acc[r].z * wgv.z + acc[r].w * wgv.w;
        p1 = wsum(p1);
        if (lane == 0) atomicAdd(&red1[r], p1);
    }
    __syncthreads();
    if (tid < QT) {
        int t = t0 + tid;
        if (t < T)
            g_gates[(size_t)b * T + t] = 1.0f / (1.0f + __expf(-(red1[tid] + bg[0])));
    }
}

// ---------- mma wrappers ----------
__device__ __forceinline__ void mma_bf16(float* c, const uint32_t* a, const uint32_t* b) {
    asm volatile("mma.sync.aligned.m16n8k16.row.col.f32.bf16.bf16.f32 "
                 "{%0,%1,%2,%3},{%4,%5,%6,%7},{%8,%9},{%0,%1,%2,%3};"
                 : "+f"(c[0]), "+f"(c[1]), "+f"(c[2]), "+f"(c[3])
                 : "r"(a[0]), "r"(a[1]), "r"(a[2]), "r"(a[3]), "r"(b[0]), "r"(b[1]));
}
__device__ __forceinline__ void cpa16(uint32_t saddr, const void* g) {
    asm volatile("cp.async.cg.shared.global [%0], [%1], 16;" :: "r"(saddr), "l"(g));
}
__device__ __forceinline__ void ldsm4(uint32_t* r, uint32_t addr) {
    asm volatile("ldmatrix.sync.aligned.m8n8.x4.shared.b16 {%0,%1,%2,%3}, [%4];"
                 : "=r"(r[0]), "=r"(r[1]), "=r"(r[2]), "=r"(r[3]) : "r"(addr));
}

// ---------- bf16 NT GEMM (R10 config): 128x128 CTA, 8 warps of 64x32, 4-stage, K-chunk 32 ----------
// outmode: 0 = fp32 store, 1 = bf16 store, 2 = fp32 atomicAdd (split-K)
#define BQ 40
#define STG 4
#define SPITCH (128 * BQ)
#define GEMM_SMEM (STG * SPITCH * 2 * 2)
__global__ __launch_bounds__(256, 2) void k_bfgemm(
    const __nv_bfloat16* __restrict__ A, const __nv_bfloat16* __restrict__ B, void* __restrict__ Cout,
    int K, int lda, int ldb, int ldc,
    long long Abat, long long Bbat, long long Cbat, int outmode,
    const float* __restrict__ coladd, int colbat)
{
    extern __shared__ __align__(16) __nv_bfloat16 dsm[];
    __nv_bfloat16* Asb = dsm;
    __nv_bfloat16* Bsb = dsm + STG * SPITCH;
    int tid = threadIdx.x, lane = tid & 31, wid = tid >> 5;
    int bz = blockIdx.z;
    A += Abat * bz; B += Bbat * bz;
    int m0 = blockIdx.y * 128, n0 = blockIdx.x * 128;
    int wm = (wid & 1) * 64, wn = (wid >> 1) * 32;
    float acc[4][4][4] = {};
    int lrow = tid >> 1, lcol = (tid & 1) * 16;
    const __nv_bfloat16* agp = A + (size_t)(m0 + lrow) * lda + lcol;
    const __nv_bfloat16* bgp = B + (size_t)(n0 + lrow) * ldb + lcol;
    int nk = K >> 5;
    int soff = lrow * BQ + lcol;
    #define LTB(kt, st) do { int _k = (kt) * 32; int _o = (st) * SPITCH + soff; \
        cpa16((uint32_t)__cvta_generic_to_shared(Asb + _o), agp + _k); \
        cpa16((uint32_t)__cvta_generic_to_shared(Asb + _o + 8), agp + _k + 8); \
        cpa16((uint32_t)__cvta_generic_to_shared(Bsb + _o), bgp + _k); \
        cpa16((uint32_t)__cvta_generic_to_shared(Bsb + _o + 8), bgp + _k + 8); \
    } while (0)

    #pragma unroll
    for (int i = 0; i < STG - 1; i++) {
        if (i < nk) LTB(i, i);
        asm volatile("cp.async.commit_group;");
    }
    int arow = (lane & 15), aoffb = (lane >> 4) * 8;
    int gq = lane >> 3;
    int brow = (gq >> 1) * 8 + (lane & 7), boffb = (gq & 1) * 8;
    for (int kt = 0; kt < nk; kt++) {
        int st = kt & (STG - 1);
        asm volatile("cp.async.wait_group %0;" :: "n"(STG - 2));
        __syncthreads();
        if (kt + STG - 1 < nk) LTB(kt + STG - 1, (kt + STG - 1) & (STG - 1));
        asm volatile("cp.async.commit_group;");
        const __nv_bfloat16* Ast = Asb + st * SPITCH;
        const __nv_bfloat16* Bst = Bsb + st * SPITCH;
        #pragma unroll
        for (int kk = 0; kk < 32; kk += 16) {
            uint32_t ar[4][4], br[4][2];
            #pragma unroll
            for (int mi = 0; mi < 4; mi++)
                ldsm4(ar[mi], (uint32_t)__cvta_generic_to_shared(
                    Ast + (wm + mi * 16 + arow) * BQ + kk + aoffb));
            #pragma unroll
            for (int nj = 0; nj < 2; nj++) {
                uint32_t t4[4];
                ldsm4(t4, (uint32_t)__cvta_generic_to_shared(
                    Bst + (wn + nj * 16 + brow) * BQ + kk + boffb));
                br[nj * 2][0] = t4[0];
                br[nj * 2][1] = t4[1];
                br[nj * 2 + 1][0] = t4[2];
                br[nj * 2 + 1][1] = t4[3];
            }
            #pragma unroll
            for (int mi = 0; mi < 4; mi++)
                #pragma unroll
                for (int ni = 0; ni < 4; ni++)
                    mma_bf16(acc[mi][ni], ar[mi], br[ni]);
        }
    }
    #pragma unroll
    for (int mi = 0; mi < 4; mi++) {
        int r0 = m0 + wm + mi * 16 + (lane >> 2);
        #pragma unroll
        for (int ni = 0; ni < 4; ni++) {
            int c0 = n0 + wn + ni * 8 + (lane & 3) * 2;
            float cb0 = coladd ? coladd[(size_t)colbat * bz + c0] : 0.f;
            float cb1 = coladd ? coladd[(size_t)colbat * bz + c0 + 1] : 0.f;
            float v00 = acc[mi][ni][0] + cb0, v01 = acc[mi][ni][1] + cb1;
            float v10 = acc[mi][ni][2] + cb0, v11 = acc[mi][ni][3] + cb1;
            if (outmode == 1) {
                __nv_bfloat16* Cb = (__nv_bfloat16*)Cout + Cbat * bz;
                *(uint32_t*)(Cb + (size_t)r0 * ldc + c0) = pkbf(v00, v01);
                *(uint32_t*)(Cb + (size_t)(r0 + 8) * ldc + c0) = pkbf(v10, v11);
            } else if (outmode == 0) {
                float* Cf = (float*)Cout + Cbat * bz;
                *(float2*)(Cf + (size_t)r0 * ldc + c0) = make_float2(v00, v01);
                *(float2*)(Cf + (size_t)(r0 + 8) * ldc + c0) = make_float2(v10, v11);
            } else {
                float* Cf = (float*)Cout;
                atomicAdd(Cf + (size_t)r0 * ldc + c0, v00);
                atomicAdd(Cf + (size_t)r0 * ldc + c0 + 1, v01);
                atomicAdd(Cf + (size_t)(r0 + 8) * ldc + c0, v10);
                atomicAdd(Cf + (size_t)(r0 + 8) * ldc + c0 + 1, v11);
            }
        }
    }
}

// ---------- final: register-resident QK softmax + windowed analytic l_att ----------
// requires S == 4 * blockDim.x
__global__ __launch_bounds__(256) void k_final(const float* __restrict__ mask_src,
                                               float* __restrict__ out,
                                               const float* __restrict__ dots,
                                               int B, int T, int S, float invscale) {
    int bt = blockIdx.x;
    int b = bt / T, t = bt - b * T;
    __shared__ float sred[32];
    __shared__ float sh_lmax, sh_linv;
    __shared__ int sh_a0, sh_a1;
    float c = g_steps[b] * (float)t;

    if (threadIdx.x < 32) {
        int ci = min(max((int)lrintf(c), 0), S - 1);
        int a0 = max(0, ci - 16), a1 = min(S - 1, ci + 16);
        float lg0 = -INFINITY, lg1 = -INFINITY;
        int s0 = a0 + (int)threadIdx.x;
        int s1 = s0 + 32;
        if (s0 <= a1) {
            float d = (float)s0 - c;
            lg0 = -(d * d) / 0.3f - INF_ * (1.0f - mask_src[(size_t)b * S + s0]);
        }
        if (s1 <= a1) {
            float d = (float)s1 - c;
            lg1 = -(d * d) / 0.3f - INF_ * (1.0f - mask_src[(size_t)b * S + s1]);
        }
        float mx = wmax(fmaxf(lg0, lg1));
        float e = 0.f;
        if (s0 <= a1) e += __expf(lg0 - mx);
        if (s1 <= a1) e += __expf(lg1 - mx);
        e = wsum(e);
        if (threadIdx.x == 0) {
            sh_lmax = mx; sh_linv = 1.0f / e; sh_a0 = a0; sh_a1 = a1;
        }
    }

    int i0 = threadIdx.x * 4;
    float4 mk = *(const float4*)(mask_src + (size_t)b * S + i0);
    float4 dv = *(const float4*)(dots + (size_t)bt * S + i0);
    float4 x;
    x.x = (dv.x - (1.0f - mk.x) * INF_) * invscale;
    x.y = (dv.y - (1.0f - mk.y) * INF_) * invscale;
    x.z = (dv.z - (1.0f - mk.z) * INF_) * invscale;
    x.w = (dv.w - (1.0f - mk.w) * INF_) * invscale;
    float qmax = fmaxf(fmaxf(x.x, x.y), fmaxf(x.z, x.w));
    qmax = bmax(qmax, sred);
    float4 e;
    e.x = __expf(x.x - qmax);
    e.y = __expf(x.y - qmax);
    e.z = __expf(x.z - qmax);
    e.w = __expf(x.w - qmax);
    float qsum = bsum(e.x + e.y + e.z + e.w, sred);
    float qinv = 1.0f / qsum;
    float g = g_gates[bt];
    float omg = 1.0f - g;
    int a0 = sh_a0, a1 = sh_a1;
    float lmax = sh_lmax, linv = sh_linv;
    float4 o;
    o.x = omg * e.x * qinv;
    o.y = omg * e.y * qinv;
    o.z = omg * e.z * qinv;
    o.w = omg * e.w * qinv;
    if (i0 + 3 >= a0 && i0 <= a1) {
        float mks[4] = {mk.x, mk.y, mk.z, mk.w};
        float* os = &o.x;
        #pragma unroll
        for (int j = 0; j < 4; j++) {
            int s = i0 + j;
            if (s >= a0 && s <= a1) {
                float d = (float)s - c;
                float lg = -(d * d) / 0.3f - INF_ * (1.0f - mks[j]);
                os[j] += g * __expf(lg - lmax) * linv;
            }
        }
    }
    *(float4*)(out + (size_t)bt * S + i0) = o;
}

// ---------- launch (multi-stream fork/join, graph-capturable) ----------
extern "C" void kernel_launch(void* const* d_in, const int* in_sizes, int n_in,
                              void* d_out, int out_size) {
    const float* key      = (const float*)d_in[0];
    const float* mask_src = (const float*)d_in[1];
    const float* mask_trg = (const float*)d_in[2];
    const float* Wq       = (const float*)d_in[3];
    const float* bq       = (const float*)d_in[4];
    const float* Wk       = (const float*)d_in[5];
    const float* bk       = (const float*)d_in[6];
    const float* wg       = (const float*)d_in[7];
    const float* bg       = (const float*)d_in[8];
    float* out = (float*)d_out;

    int D  = in_sizes[4];
    int BT = in_sizes[2];
    int S  = out_size / BT;
    int B  = in_sizes[1] / S;
    int T  = BT / B;

    float *p_Mt, *p_bs, *p_dots;
    __nv_bfloat16 *p_keyB, *p_queryB, *p_qmB, *p_MtB, *p_WqTB, *p_WkTB;
    cudaGetSymbolAddress((void**)&p_Mt,    g_Mt);
    cudaGetSymbolAddress((void**)&p_bs,    g_bs);
    cudaGetSymbolAddress((void**)&p_dots,  g_dots);
    cudaGetSymbolAddress((void**)&p_keyB,  g_keyB);
    cudaGetSymbolAddress((void**)&p_queryB, g_queryB);
    cudaGetSymbolAddress((void**)&p_qmB,   g_qmB);
    cudaGetSymbolAddress((void**)&p_MtB,   g_MtB);
    cudaGetSymbolAddress((void**)&p_WqTB,  g_WqTB);
    cudaGetSymbolAddress((void**)&p_WkTB,  g_WkTB);

    static cudaStream_t sA = nullptr, sB = nullptr;
    static cudaEvent_t eT = nullptr, eC = nullptr, eM = nullptr, eK = nullptr;
    if (!sA) {
        cudaStreamCreateWithFlags(&sA, cudaStreamNonBlocking);
        cudaStreamCreateWithFlags(&sB, cudaStreamNonBlocking);
        cudaEventCreateWithFlags(&eT, cudaEventDisableTiming);
        cudaEventCreateWithFlags(&eC, cudaEventDisableTiming);
        cudaEventCreateWithFlags(&eM, cudaEventDisableTiming);
        cudaEventCreateWithFlags(&eK, cudaEventDisableTiming);
        cudaFuncSetAttribute(k_bfgemm, cudaFuncAttributeMaxDynamicSharedMemorySize, GEMM_SMEM);
    }

    // main stream: transpose Wq/Wk (+ zero Mt)
    {
        dim3 tb(32, 8);
        dim3 g(D / 32, D / 32, 2);
        k_transp2<<<g, tb>>>(Wq, Wk, D);
    }
    cudaEventRecord(eT, 0);

    // main: c2 + steps
    k_cvecR<<<D, 128>>>(bq, mask_src, mask_trg, D, B, S, T);
    cudaEventRecord(eC, 0);

    // side stream A (after transp2): Mt split-K + cvt -> MtB
    cudaStreamWaitEvent(sA, eT, 0);
    {
        dim3 g(D / 128, D / 128, 4);
        k_bfgemm<<<g, 256, GEMM_SMEM, sA>>>(p_WkTB, p_WqTB, p_Mt, D / 4, D, D, D,
                                            D / 4, D / 4, 0, 2, nullptr, 0);
    }
    k_cvt<<<(D * D / 4 + 255) / 256, 256, 0, sA>>>(p_Mt, p_MtB, D * D / 4);
    cudaEventRecord(eM, sA);

    // side stream B (after c2): bs + keyB
    cudaStreamWaitEvent(sB, eC, 0);
    k_bskey<<<B * S, 128, 0, sB>>>(key, D);
    cudaEventRecord(eK, sB);

    // main (after steps): windowed query + gates  — overlaps with streams A/B
    {
        dim3 g((T + QT - 1) / QT, B);
        k_query<<<g, 256>>>(mask_src, key, wg, bg, B, T, S, D);
    }

    // main: qm = queryB @ MtB^T  (needs MtB)
    cudaStreamWaitEvent(0, eM, 0);
    {
        dim3 g(D / 128, BT / 128, 1);
        k_bfgemm<<<g, 256, GEMM_SMEM>>>(p_queryB, p_MtB, p_qmB, D, D, D, D,
                                        0, 0, 0, 1, nullptr, 0);
    }

    // main: dots = qmB @ keyB^T + bs  (needs keyB/bs)
    cudaStreamWaitEvent(0, eK, 0);
    {
        dim3 g(S / 128, T / 128, B);
        k_bfgemm<<<g, 256, GEMM_SMEM>>>(p_qmB, p_keyB, p_dots, D, D, D, S,
                                        (long long)T * D, (long long)S * D, (long long)T * S, 0,
                                        p_bs, S);
    }

    // main: final
    k_final<<<B * T, S / 4>>>(mask_src, out, p_dots, B, T, S, 1.0f / sqrtf((float)D));
}

// round 16
// speedup vs baseline: 1.3683x; 1.0036x over previous
#include <cuda_runtime.h>
#include <cuda_bf16.h>
#include <stdint.h>
#include <math.h>

#define INF_ 1e10f

__device__ float g_dots [8388608];
__device__ float g_Mt   [1048576];
__device__ float g_WqT  [1048576];
__device__ float g_WkT  [1048576];
__device__ float g_c2   [1024];
__device__ float g_steps[64];
__device__ float g_bs   [8192];
__device__ float g_gates[8192];
__device__ __nv_bfloat16 g_keyB  [8388608];
__device__ __nv_bfloat16 g_queryB[8388608];
__device__ __nv_bfloat16 g_qmB   [8388608];
__device__ __nv_bfloat16 g_MtB   [1048576];
__device__ __nv_bfloat16 g_WqTB  [1048576];
__device__ __nv_bfloat16 g_WkTB  [1048576];

// ---------- helpers ----------
__device__ __forceinline__ uint32_t pkbf(float a, float b) {
    __nv_bfloat162 t = __halves2bfloat162(__float2bfloat16(a), __float2bfloat16(b));
    return *reinterpret_cast<uint32_t*>(&t);
}
__device__ __forceinline__ float wsum(float v) {
    #pragma unroll
    for (int o = 16; o; o >>= 1) v += __shfl_xor_sync(0xffffffffu, v, o);
    return v;
}
__device__ __forceinline__ float wmax(float v) {
    #pragma unroll
    for (int o = 16; o; o >>= 1) v = fmaxf(v, __shfl_xor_sync(0xffffffffu, v, o));
    return v;
}
__device__ float bsum(float v, float* sb) {
    int lane = threadIdx.x & 31, w = threadIdx.x >> 5, nw = (blockDim.x + 31) >> 5;
    v = wsum(v);
    if (lane == 0) sb[w] = v;
    __syncthreads();
    v = (threadIdx.x < nw) ? sb[threadIdx.x] : 0.f;
    if (w == 0) v = wsum(v);
    if (threadIdx.x == 0) sb[0] = v;
    __syncthreads();
    v = sb[0];
    __syncthreads();
    return v;
}
__device__ float bmax(float v, float* sb) {
    int lane = threadIdx.x & 31, w = threadIdx.x >> 5, nw = (blockDim.x + 31) >> 5;
    v = wmax(v);
    if (lane == 0) sb[w] = v;
    __syncthreads();
    v = (threadIdx.x < nw) ? sb[threadIdx.x] : -INFINITY;
    if (w == 0) v = wmax(v);
    if (threadIdx.x == 0) sb[0] = v;
    __syncthreads();
    v = sb[0];
    __syncthreads();
    return v;
}

// ---------- small kernels ----------
__global__ void k_steps(const float* __restrict__ ms, const float* __restrict__ mt,
                        int S, int T) {
    __shared__ float sb[32];
    int b = blockIdx.x;
    float s = 0.f;
    for (int i = threadIdx.x; i < S; i += blockDim.x) s += ms[(size_t)b * S + i];
    s = bsum(s, sb);
    float t = 0.f;
    for (int i = threadIdx.x; i < T; i += blockDim.x) t += mt[(size_t)b * T + i];
    t = bsum(t, sb);
    if (threadIdx.x == 0) g_steps[b] = s / t;
}

__global__ void k_cvt(const float* __restrict__ in, __nv_bfloat16* __restrict__ o, int n4) {
    int i = blockIdx.x * blockDim.x + threadIdx.x;
    if (i >= n4) return;
    float4 v = ((const float4*)in)[i];
    uint2 p;
    p.x = pkbf(v.x, v.y);
    p.y = pkbf(v.z, v.w);
    *(uint2*)(o + (size_t)i * 4) = p;
}

// transpose Wq (z=0) / Wk (z=1) -> fp32 + bf16; also zero g_Mt
__global__ void k_transp2(const float* __restrict__ Wq, const float* __restrict__ Wk, int D) {
    __shared__ float t[32][33];
    const float* in = blockIdx.z ? Wk : Wq;
    float* outp = blockIdx.z ? g_WkT : g_WqT;
    __nv_bfloat16* outb = blockIdx.z ? g_WkTB : g_WqTB;
    int x0 = blockIdx.x * 32, y0 = blockIdx.y * 32;
    int tx = threadIdx.x, ty = threadIdx.y;
    int tid = ty * 32 + tx;
    int bid = blockIdx.x + 32 * (blockIdx.y + 32 * blockIdx.z);
    if (tid < 128)
        ((float4*)g_Mt)[(size_t)bid * 128 + tid] = make_float4(0.f, 0.f, 0.f, 0.f);
    #pragma unroll
    for (int j = 0; j < 32; j += 8)
        t[ty + j][tx] = in[(size_t)(y0 + ty + j) * D + x0 + tx];
    __syncthreads();
    #pragma unroll
    for (int j = 0; j < 32; j += 8) {
        float v = t[tx][ty + j];
        size_t idx = (size_t)(x0 + ty + j) * D + y0 + tx;
        outp[idx] = v;
        outb[idx] = __float2bfloat16(v);
    }
}

// c2[e] = dot(WkT[e,:], bq)
__global__ void k_cvecR(const float* __restrict__ bq, int D) {
    int e = blockIdx.x;
    __shared__ float sb[32];
    const float4* r2 = (const float4*)(g_WkT + (size_t)e * D);
    float s2 = 0.f;
    for (int i = threadIdx.x; i < D / 4; i += blockDim.x) {
        float4 b2 = r2[i], d2 = *(const float4*)(bq + i * 4);
        s2 += b2.x * d2.x + b2.y * d2.y + b2.z * d2.z + b2.w * d2.w;
    }
    s2 = bsum(s2, sb);
    if (threadIdx.x == 0) g_c2[e] = s2;
}

__global__ void k_bskey(const float* __restrict__ key, int D) {
    int r = blockIdx.x;
    __shared__ float sb[32];
    float s = 0.f;
    const float4* kr = (const float4*)(key + (size_t)r * D);
    uint2* ob = (uint2*)(g_keyB + (size_t)r * D);
    for (int i = threadIdx.x; i < D / 4; i += blockDim.x) {
        float4 kv = kr[i], cv = *(const float4*)(g_c2 + i * 4);
        s += kv.x * cv.x + kv.y * cv.y + kv.z * cv.z + kv.w * cv.w;
        uint2 p;
        p.x = pkbf(kv.x, kv.y);
        p.y = pkbf(kv.z, kv.w);
        ob[i] = p;
    }
    s = bsum(s, sb);
    if (threadIdx.x == 0) g_bs[r] = s;
}

// ---------- windowed query = l_att @ key, fused gates ----------
#define QT 16
__global__ __launch_bounds__(256) void k_query(const float* __restrict__ mask_src,
                                               const float* __restrict__ key,
                                               const float* __restrict__ wg,
                                               const float* __restrict__ bg,
                                               int B, int T, int S, int D) {
    __shared__ float wk[QT][64];
    __shared__ float s_c[QT], s_m[QT], s_inv[QT];
    __shared__ int s_s0[QT], s_s1[QT], sh_lo, sh_hi;
    __shared__ float red1[QT];
    int b = blockIdx.y, t0 = blockIdx.x * QT, tid = threadIdx.x;
    int lane = tid & 31;
    float step = g_steps[b];
    if (tid < QT) {
        red1[tid] = 0.f;
        int t = t0 + tid;
        if (t < T) {
            float c = step * (float)t;
            int ci = (int)lrintf(c);
            ci = min(max(ci, 0), S - 1);
            int a0 = max(0, ci - 16), a1 = min(S - 1, ci + 16);
            float mx = -INFINITY;
            for (int s = a0; s <= a1; s++) {
                float d = (float)s - c;
                mx = fmaxf(mx, -(d * d) / 0.3f - INF_ * (1.0f - mask_src[(size_t)b * S + s]));
            }
            float sum = 0.f;
            for (int s = a0; s <= a1; s++) {
                float d = (float)s - c;
                sum += __expf(-(d * d) / 0.3f - INF_ * (1.0f - mask_src[(size_t)b * S + s]) - mx);
            }
            s_c[tid] = c; s_m[tid] = mx; s_inv[tid] = 1.0f / sum;
            s_s0[tid] = a0; s_s1[tid] = a1;
        } else {
            s_c[tid] = 0.f; s_m[tid] = 0.f; s_inv[tid] = 0.f;
            s_s0[tid] = 1; s_s1[tid] = 0;
        }
    }
    __syncthreads();
    if (tid == 0) {
        int lo = s_s0[0], hi = s_s1[0];
        for (int i = 1; i < QT; i++)
            if (s_s1[i] >= s_s0[i]) { lo = min(lo, s_s0[i]); hi = max(hi, s_s1[i]); }
        sh_lo = lo; sh_hi = hi;
    }
    __syncthreads();
    int lo = sh_lo, hi = sh_hi;
    float4 acc[QT];
    #pragma unroll
    for (int r = 0; r < QT; r++) acc[r] = make_float4(0.f, 0.f, 0.f, 0.f);
    for (int c0 = lo; c0 <= hi; c0 += 64) {
        int cnt = min(64, hi - c0 + 1);
        __syncthreads();
        for (int i = tid; i < QT * 64; i += 256) {
            int tr = i >> 6, j = i & 63, s = c0 + j;
            float w = 0.f;
            if (j < cnt && s >= s_s0[tr] && s <= s_s1[tr]) {
                float d = (float)s - s_c[tr];
                w = __expf(-(d * d) / 0.3f - INF_ * (1.0f - mask_src[(size_t)b * S + s]) - s_m[tr]) * s_inv[tr];
            }
            wk[tr][j] = w;
        }
        __syncthreads();
        for (int j = 0; j < cnt; j++) {
            float4 kv = *(const float4*)(key + ((size_t)b * S + c0 + j) * D + tid * 4);
            #pragma unroll
            for (int r = 0; r < QT; r++) {
                float w = wk[r][j];
                acc[r].x = fmaf(w, kv.x, acc[r].x);
                acc[r].y = fmaf(w, kv.y, acc[r].y);
                acc[r].z = fmaf(w, kv.z, acc[r].z);
                acc[r].w = fmaf(w, kv.w, acc[r].w);
            }
        }
        __syncthreads();
    }
    float4 wgv = *(const float4*)(wg + tid * 4);
    #pragma unroll
    for (int r = 0; r < QT; r++) {
        int t = t0 + r;
        if (t < T) {
            size_t base = ((size_t)b * T + t) * D + tid * 4;
            uint2 p;
            p.x = pkbf(acc[r].x, acc[r].y);
            p.y = pkbf(acc[r].z, acc[r].w);
            *(uint2*)(g_queryB + base) = p;
        }
        float p1 = acc[r].x * wgv.x + acc[r].y * wgv.y + acc[r].z * wgv.z + acc[r].w * wgv.w;
        p1 = wsum(p1);
        if (lane == 0) atomicAdd(&red1[r], p1);
    }
    __syncthreads();
    if (tid < QT) {
        int t = t0 + tid;
        if (t < T)
            g_gates[(size_t)b * T + t] = 1.0f / (1.0f + __expf(-(red1[tid] + bg[0])));
    }
}

// ---------- mma wrappers ----------
__device__ __forceinline__ void mma_bf16(float* c, const uint32_t* a, const uint32_t* b) {
    asm volatile("mma.sync.aligned.m16n8k16.row.col.f32.bf16.bf16.f32 "
                 "{%0,%1,%2,%3},{%4,%5,%6,%7},{%8,%9},{%0,%1,%2,%3};"
                 : "+f"(c[0]), "+f"(c[1]), "+f"(c[2]), "+f"(c[3])
                 : "r"(a[0]), "r"(a[1]), "r"(a[2]), "r"(a[3]), "r"(b[0]), "r"(b[1]));
}
__device__ __forceinline__ void cpa16(uint32_t saddr, const void* g) {
    asm volatile("cp.async.cg.shared.global [%0], [%1], 16;" :: "r"(saddr), "l"(g));
}
__device__ __forceinline__ void ldsm4(uint32_t* r, uint32_t addr) {
    asm volatile("ldmatrix.sync.aligned.m8n8.x4.shared.b16 {%0,%1,%2,%3}, [%4];"
                 : "=r"(r[0]), "=r"(r[1]), "=r"(r[2]), "=r"(r[3]) : "r"(addr));
}

// ---------- bf16 NT GEMM (R10 config): 128x128 CTA, 8 warps of 64x32, 4-stage, K-chunk 32 ----------
// outmode: 0 = fp32 store, 1 = bf16 store, 2 = fp32 atomicAdd (split-K)
#define BQ 40
#define STG 4
#define SPITCH (128 * BQ)
#define GEMM_SMEM (STG * SPITCH * 2 * 2)
__global__ __launch_bounds__(256, 2) void k_bfgemm(
    const __nv_bfloat16* __restrict__ A, const __nv_bfloat16* __restrict__ B, void* __restrict__ Cout,
    int K, int lda, int ldb, int ldc,
    long long Abat, long long Bbat, long long Cbat, int outmode,
    const float* __restrict__ coladd, int colbat)
{
    extern __shared__ __align__(16) __nv_bfloat16 dsm[];
    __nv_bfloat16* Asb = dsm;
    __nv_bfloat16* Bsb = dsm + STG * SPITCH;
    int tid = threadIdx.x, lane = tid & 31, wid = tid >> 5;
    int bz = blockIdx.z;
    A += Abat * bz; B += Bbat * bz;
    int m0 = blockIdx.y * 128, n0 = blockIdx.x * 128;
    int wm = (wid & 1) * 64, wn = (wid >> 1) * 32;
    float acc[4][4][4] = {};
    int lrow = tid >> 1, lcol = (tid & 1) * 16;
    const __nv_bfloat16* agp = A + (size_t)(m0 + lrow) * lda + lcol;
    const __nv_bfloat16* bgp = B + (size_t)(n0 + lrow) * ldb + lcol;
    int nk = K >> 5;
    int soff = lrow * BQ + lcol;
    #define LTB(kt, st) do { int _k = (kt) * 32; int _o = (st) * SPITCH + soff; \
        cpa16((uint32_t)__cvta_generic_to_shared(Asb + _o), agp + _k); \
        cpa16((uint32_t)__cvta_generic_to_shared(Asb + _o + 8), agp + _k + 8); \
        cpa16((uint32_t)__cvta_generic_to_shared(Bsb + _o), bgp + _k); \
        cpa16((uint32_t)__cvta_generic_to_shared(Bsb + _o + 8), bgp + _k + 8); \
    } while (0)

    #pragma unroll
    for (int i = 0; i < STG - 1; i++) {
        if (i < nk) LTB(i, i);
        asm volatile("cp.async.commit_group;");
    }
    int arow = (lane & 15), aoffb = (lane >> 4) * 8;
    int gq = lane >> 3;
    int brow = (gq >> 1) * 8 + (lane & 7), boffb = (gq & 1) * 8;
    for (int kt = 0; kt < nk; kt++) {
        int st = kt & (STG - 1);
        asm volatile("cp.async.wait_group %0;" :: "n"(STG - 2));
        __syncthreads();
        if (kt + STG - 1 < nk) LTB(kt + STG - 1, (kt + STG - 1) & (STG - 1));
        asm volatile("cp.async.commit_group;");
        const __nv_bfloat16* Ast = Asb + st * SPITCH;
        const __nv_bfloat16* Bst = Bsb + st * SPITCH;
        #pragma unroll
        for (int kk = 0; kk < 32; kk += 16) {
            uint32_t ar[4][4], br[4][2];
            #pragma unroll
            for (int mi = 0; mi < 4; mi++)
                ldsm4(ar[mi], (uint32_t)__cvta_generic_to_shared(
                    Ast + (wm + mi * 16 + arow) * BQ + kk + aoffb));
            #pragma unroll
            for (int nj = 0; nj < 2; nj++) {
                uint32_t t4[4];
                ldsm4(t4, (uint32_t)__cvta_generic_to_shared(
                    Bst + (wn + nj * 16 + brow) * BQ + kk + boffb));
                br[nj * 2][0] = t4[0];
                br[nj * 2][1] = t4[1];
                br[nj * 2 + 1][0] = t4[2];
                br[nj * 2 + 1][1] = t4[3];
            }
            #pragma unroll
            for (int mi = 0; mi < 4; mi++)
                #pragma unroll
                for (int ni = 0; ni < 4; ni++)
                    mma_bf16(acc[mi][ni], ar[mi], br[ni]);
        }
    }
    #pragma unroll
    for (int mi = 0; mi < 4; mi++) {
        int r0 = m0 + wm + mi * 16 + (lane >> 2);
        #pragma unroll
        for (int ni = 0; ni < 4; ni++) {
            int c0 = n0 + wn + ni * 8 + (lane & 3) * 2;
            float cb0 = coladd ? coladd[(size_t)colbat * bz + c0] : 0.f;
            float cb1 = coladd ? coladd[(size_t)colbat * bz + c0 + 1] : 0.f;
            float v00 = acc[mi][ni][0] + cb0, v01 = acc[mi][ni][1] + cb1;
            float v10 = acc[mi][ni][2] + cb0, v11 = acc[mi][ni][3] + cb1;
            if (outmode == 1) {
                __nv_bfloat16* Cb = (__nv_bfloat16*)Cout + Cbat * bz;
                *(uint32_t*)(Cb + (size_t)r0 * ldc + c0) = pkbf(v00, v01);
                *(uint32_t*)(Cb + (size_t)(r0 + 8) * ldc + c0) = pkbf(v10, v11);
            } else if (outmode == 0) {
                float* Cf = (float*)Cout + Cbat * bz;
                *(float2*)(Cf + (size_t)r0 * ldc + c0) = make_float2(v00, v01);
                *(float2*)(Cf + (size_t)(r0 + 8) * ldc + c0) = make_float2(v10, v11);
            } else {
                float* Cf = (float*)Cout;
                atomicAdd(Cf + (size_t)r0 * ldc + c0, v00);
                atomicAdd(Cf + (size_t)r0 * ldc + c0 + 1, v01);
                atomicAdd(Cf + (size_t)(r0 + 8) * ldc + c0, v10);
                atomicAdd(Cf + (size_t)(r0 + 8) * ldc + c0 + 1, v11);
            }
        }
    }
}

// ---------- final: register-resident QK softmax + windowed analytic l_att ----------
// requires S == 4 * blockDim.x; processes bt = bt_base + blockIdx.x
__global__ __launch_bounds__(256) void k_final(const float* __restrict__ mask_src,
                                               float* __restrict__ out,
                                               const float* __restrict__ dots,
                                               int B, int T, int S, float invscale,
                                               int bt_base) {
    int bt = bt_base + blockIdx.x;
    int b = bt / T, t = bt - b * T;
    __shared__ float sred[32];
    __shared__ float sh_lmax, sh_linv;
    __shared__ int sh_a0, sh_a1;
    float c = g_steps[b] * (float)t;

    if (threadIdx.x < 32) {
        int ci = min(max((int)lrintf(c), 0), S - 1);
        int a0 = max(0, ci - 16), a1 = min(S - 1, ci + 16);
        float lg0 = -INFINITY, lg1 = -INFINITY;
        int s0 = a0 + (int)threadIdx.x;
        int s1 = s0 + 32;
        if (s0 <= a1) {
            float d = (float)s0 - c;
            lg0 = -(d * d) / 0.3f - INF_ * (1.0f - mask_src[(size_t)b * S + s0]);
        }
        if (s1 <= a1) {
            float d = (float)s1 - c;
            lg1 = -(d * d) / 0.3f - INF_ * (1.0f - mask_src[(size_t)b * S + s1]);
        }
        float mx = wmax(fmaxf(lg0, lg1));
        float e = 0.f;
        if (s0 <= a1) e += __expf(lg0 - mx);
        if (s1 <= a1) e += __expf(lg1 - mx);
        e = wsum(e);
        if (threadIdx.x == 0) {
            sh_lmax = mx; sh_linv = 1.0f / e; sh_a0 = a0; sh_a1 = a1;
        }
    }

    int i0 = threadIdx.x * 4;
    float4 mk = *(const float4*)(mask_src + (size_t)b * S + i0);
    float4 dv = *(const float4*)(dots + (size_t)bt * S + i0);
    float4 x;
    x.x = (dv.x - (1.0f - mk.x) * INF_) * invscale;
    x.y = (dv.y - (1.0f - mk.y) * INF_) * invscale;
    x.z = (dv.z - (1.0f - mk.z) * INF_) * invscale;
    x.w = (dv.w - (1.0f - mk.w) * INF_) * invscale;
    float qmax = fmaxf(fmaxf(x.x, x.y), fmaxf(x.z, x.w));
    qmax = bmax(qmax, sred);
    float4 e;
    e.x = __expf(x.x - qmax);
    e.y = __expf(x.y - qmax);
    e.z = __expf(x.z - qmax);
    e.w = __expf(x.w - qmax);
    float qsum = bsum(e.x + e.y + e.z + e.w, sred);
    float qinv = 1.0f / qsum;
    float g = g_gates[bt];
    float omg = 1.0f - g;
    int a0 = sh_a0, a1 = sh_a1;
    float lmax = sh_lmax, linv = sh_linv;
    float4 o;
    o.x = omg * e.x * qinv;
    o.y = omg * e.y * qinv;
    o.z = omg * e.z * qinv;
    o.w = omg * e.w * qinv;
    if (i0 + 3 >= a0 && i0 <= a1) {
        float mks[4] = {mk.x, mk.y, mk.z, mk.w};
        float* os = &o.x;
        #pragma unroll
        for (int j = 0; j < 4; j++) {
            int s = i0 + j;
            if (s >= a0 && s <= a1) {
                float d = (float)s - c;
                float lg = -(d * d) / 0.3f - INF_ * (1.0f - mks[j]);
                os[j] += g * __expf(lg - lmax) * linv;
            }
        }
    }
    *(float4*)(out + (size_t)bt * S + i0) = o;
}

// ---------- launch (multi-stream fork/join, graph-capturable) ----------
extern "C" void kernel_launch(void* const* d_in, const int* in_sizes, int n_in,
                              void* d_out, int out_size) {
    const float* key      = (const float*)d_in[0];
    const float* mask_src = (const float*)d_in[1];
    const float* mask_trg = (const float*)d_in[2];
    const float* Wq       = (const float*)d_in[3];
    const float* bq       = (const float*)d_in[4];
    const float* Wk       = (const float*)d_in[5];
    const float* bk       = (const float*)d_in[6];
    const float* wg       = (const float*)d_in[7];
    const float* bg       = (const float*)d_in[8];
    float* out = (float*)d_out;

    int D  = in_sizes[4];
    int BT = in_sizes[2];
    int S  = out_size / BT;
    int B  = in_sizes[1] / S;
    int T  = BT / B;
    int Bh = B / 2;

    float *p_Mt, *p_bs, *p_dots;
    __nv_bfloat16 *p_keyB, *p_queryB, *p_qmB, *p_MtB, *p_WqTB, *p_WkTB;
    cudaGetSymbolAddress((void**)&p_Mt,    g_Mt);
    cudaGetSymbolAddress((void**)&p_bs,    g_bs);
    cudaGetSymbolAddress((void**)&p_dots,  g_dots);
    cudaGetSymbolAddress((void**)&p_keyB,  g_keyB);
    cudaGetSymbolAddress((void**)&p_queryB, g_queryB);
    cudaGetSymbolAddress((void**)&p_qmB,   g_qmB);
    cudaGetSymbolAddress((void**)&p_MtB,   g_MtB);
    cudaGetSymbolAddress((void**)&p_WqTB,  g_WqTB);
    cudaGetSymbolAddress((void**)&p_WkTB,  g_WkTB);

    static cudaStream_t sA = nullptr, sB = nullptr;
    static cudaEvent_t e0 = nullptr, eT = nullptr, eM = nullptr, eK = nullptr,
                       eD1 = nullptr, eF1 = nullptr;
    if (!sA) {
        cudaStreamCreateWithFlags(&sA, cudaStreamNonBlocking);
        cudaStreamCreateWithFlags(&sB, cudaStreamNonBlocking);
        cudaEventCreateWithFlags(&e0, cudaEventDisableTiming);
        cudaEventCreateWithFlags(&eT, cudaEventDisableTiming);
        cudaEventCreateWithFlags(&eM, cudaEventDisableTiming);
        cudaEventCreateWithFlags(&eK, cudaEventDisableTiming);
        cudaEventCreateWithFlags(&eD1, cudaEventDisableTiming);
        cudaEventCreateWithFlags(&eF1, cudaEventDisableTiming);
        cudaFuncSetAttribute(k_bfgemm, cudaFuncAttributeMaxDynamicSharedMemorySize, GEMM_SMEM);
    }

    long long Abat = (long long)T * D;
    long long Bbat = (long long)S * D;
    long long Cbat = (long long)T * S;

    // main: steps (tiny) -> query starts early
    k_steps<<<B, 256>>>(mask_src, mask_trg, S, T);
    cudaEventRecord(e0, 0);

    // stream A (fork at e0): transp2 -> Mt split-K -> cvt -> eM
    cudaStreamWaitEvent(sA, e0, 0);
    {
        dim3 tb(32, 8);
        dim3 g(D / 32, D / 32, 2);
        k_transp2<<<g, tb, 0, sA>>>(Wq, Wk, D);
    }
    cudaEventRecord(eT, sA);
    {
        dim3 g(D / 128, D / 128, 4);
        k_bfgemm<<<g, 256, GEMM_SMEM, sA>>>(p_WkTB, p_WqTB, p_Mt, D / 4, D, D, D,
                                            D / 4, D / 4, 0, 2, nullptr, 0);
    }
    k_cvt<<<(D * D / 4 + 255) / 256, 256, 0, sA>>>(p_Mt, p_MtB, D * D / 4);
    cudaEventRecord(eM, sA);

    // stream B (fork at eT): c2 -> bskey -> eK
    cudaStreamWaitEvent(sB, eT, 0);
    k_cvecR<<<D, 128, 0, sB>>>(bq, D);
    k_bskey<<<B * S, 128, 0, sB>>>(key, D);
    cudaEventRecord(eK, sB);

    // main: windowed query + gates (overlaps streams A/B)
    {
        dim3 g((T + QT - 1) / QT, B);
        k_query<<<g, 256>>>(mask_src, key, wg, bg, B, T, S, D);
    }

    // main: qm = queryB @ MtB^T (needs MtB)
    cudaStreamWaitEvent(0, eM, 0);
    {
        dim3 g(D / 128, BT / 128, 1);
        k_bfgemm<<<g, 256, GEMM_SMEM>>>(p_queryB, p_MtB, p_qmB, D, D, D, D,
                                        0, 0, 0, 1, nullptr, 0);
    }

    // main: dots half 1 (batches 0..Bh-1), needs keyB/bs
    cudaStreamWaitEvent(0, eK, 0);
    {
        dim3 g(S / 128, T / 128, Bh);
        k_bfgemm<<<g, 256, GEMM_SMEM>>>(p_qmB, p_keyB, p_dots, D, D, D, S,
                                        Abat, Bbat, Cbat, 0, p_bs, S);
    }
    cudaEventRecord(eD1, 0);

    // main: dots half 2 (batches Bh..B-1) via pointer offsets
    {
        dim3 g(S / 128, T / 128, B - Bh);
        k_bfgemm<<<g, 256, GEMM_SMEM>>>(p_qmB + (size_t)Bh * Abat, p_keyB + (size_t)Bh * Bbat,
                                        p_dots + (size_t)Bh * Cbat, D, D, D, S,
                                        Abat, Bbat, Cbat, 0, p_bs + (size_t)Bh * S, S);
    }

    // stream B: final half 1 overlaps dots half 2
    cudaStreamWaitEvent(sB, eD1, 0);
    k_final<<<Bh * T, S / 4, 0, sB>>>(mask_src, out, p_dots, B, T, S,
                                      1.0f / sqrtf((float)D), 0);
    cudaEventRecord(eF1, sB);

    // main: final half 2, joined after final half 1
    cudaStreamWaitEvent(0, eF1, 0);
    k_final<<<(B - Bh) * T, S / 4>>>(mask_src, out, p_dots, B, T, S,
                                     1.0f / sqrtf((float)D), Bh * T);
}

// round 17
// speedup vs baseline: 1.4051x; 1.0269x over previous
#include <cuda_runtime.h>
#include <cuda_bf16.h>
#include <stdint.h>
#include <math.h>

#define INF_ 1e10f

__device__ float g_dots [8388608];
__device__ float g_Mt   [1048576];
__device__ float g_WqT  [1048576];
__device__ float g_WkT  [1048576];
__device__ float g_c2   [1024];
__device__ float g_steps[64];
__device__ float g_bs   [8192];
__device__ float g_gates[8192];
__device__ __nv_bfloat16 g_keyB  [8388608];
__device__ __nv_bfloat16 g_queryB[8388608];
__device__ __nv_bfloat16 g_qmB   [8388608];
__device__ __nv_bfloat16 g_MtB   [1048576];
__device__ __nv_bfloat16 g_WqTB  [1048576];
__device__ __nv_bfloat16 g_WkTB  [1048576];

// ---------- helpers ----------
__device__ __forceinline__ uint32_t pkbf(float a, float b) {
    __nv_bfloat162 t = __halves2bfloat162(__float2bfloat16(a), __float2bfloat16(b));
    return *reinterpret_cast<uint32_t*>(&t);
}
__device__ __forceinline__ float wsum(float v) {
    #pragma unroll
    for (int o = 16; o; o >>= 1) v += __shfl_xor_sync(0xffffffffu, v, o);
    return v;
}
__device__ __forceinline__ float wmax(float v) {
    #pragma unroll
    for (int o = 16; o; o >>= 1) v = fmaxf(v, __shfl_xor_sync(0xffffffffu, v, o));
    return v;
}
__device__ float bsum(float v, float* sb) {
    int lane = threadIdx.x & 31, w = threadIdx.x >> 5, nw = (blockDim.x + 31) >> 5;
    v = wsum(v);
    if (lane == 0) sb[w] = v;
    __syncthreads();
    v = (threadIdx.x < nw) ? sb[threadIdx.x] : 0.f;
    if (w == 0) v = wsum(v);
    if (threadIdx.x == 0) sb[0] = v;
    __syncthreads();
    v = sb[0];
    __syncthreads();
    return v;
}
__device__ float bmax(float v, float* sb) {
    int lane = threadIdx.x & 31, w = threadIdx.x >> 5, nw = (blockDim.x + 31) >> 5;
    v = wmax(v);
    if (lane == 0) sb[w] = v;
    __syncthreads();
    v = (threadIdx.x < nw) ? sb[threadIdx.x] : -INFINITY;
    if (w == 0) v = wmax(v);
    if (threadIdx.x == 0) sb[0] = v;
    __syncthreads();
    v = sb[0];
    __syncthreads();
    return v;
}

// ---------- small kernels ----------
__global__ void k_steps(const float* __restrict__ ms, const float* __restrict__ mt,
                        int S, int T) {
    __shared__ float sb[32];
    int b = blockIdx.x;
    float s = 0.f;
    for (int i = threadIdx.x; i < S; i += blockDim.x) s += ms[(size_t)b * S + i];
    s = bsum(s, sb);
    float t = 0.f;
    for (int i = threadIdx.x; i < T; i += blockDim.x) t += mt[(size_t)b * T + i];
    t = bsum(t, sb);
    if (threadIdx.x == 0) g_steps[b] = s / t;
}

__global__ void k_cvt(const float* __restrict__ in, __nv_bfloat16* __restrict__ o, int n4) {
    int i = blockIdx.x * blockDim.x + threadIdx.x;
    if (i >= n4) return;
    float4 v = ((const float4*)in)[i];
    uint2 p;
    p.x = pkbf(v.x, v.y);
    p.y = pkbf(v.z, v.w);
    *(uint2*)(o + (size_t)i * 4) = p;
}

__global__ void k_transp2(const float* __restrict__ Wq, const float* __restrict__ Wk, int D) {
    __shared__ float t[32][33];
    const float* in = blockIdx.z ? Wk : Wq;
    float* outp = blockIdx.z ? g_WkT : g_WqT;
    __nv_bfloat16* outb = blockIdx.z ? g_WkTB : g_WqTB;
    int x0 = blockIdx.x * 32, y0 = blockIdx.y * 32;
    int tx = threadIdx.x, ty = threadIdx.y;
    int tid = ty * 32 + tx;
    int bid = blockIdx.x + 32 * (blockIdx.y + 32 * blockIdx.z);
    if (tid < 128)
        ((float4*)g_Mt)[(size_t)bid * 128 + tid] = make_float4(0.f, 0.f, 0.f, 0.f);
    #pragma unroll
    for (int j = 0; j < 32; j += 8)
        t[ty + j][tx] = in[(size_t)(y0 + ty + j) * D + x0 + tx];
    __syncthreads();
    #pragma unroll
    for (int j = 0; j < 32; j += 8) {
        float v = t[tx][ty + j];
        size_t idx = (size_t)(x0 + ty + j) * D + y0 + tx;
        outp[idx] = v;
        outb[idx] = __float2bfloat16(v);
    }
}

__global__ void k_cvecR(const float* __restrict__ bq, int D) {
    int e = blockIdx.x;
    __shared__ float sb[32];
    const float4* r2 = (const float4*)(g_WkT + (size_t)e * D);
    float s2 = 0.f;
    for (int i = threadIdx.x; i < D / 4; i += blockDim.x) {
        float4 b2 = r2[i], d2 = *(const float4*)(bq + i * 4);
        s2 += b2.x * d2.x + b2.y * d2.y + b2.z * d2.z + b2.w * d2.w;
    }
    s2 = bsum(s2, sb);
    if (threadIdx.x == 0) g_c2[e] = s2;
}

__global__ void k_bskey(const float* __restrict__ key, int D) {
    int r = blockIdx.x;
    __shared__ float sb[32];
    float s = 0.f;
    const float4* kr = (const float4*)(key + (size_t)r * D);
    uint2* ob = (uint2*)(g_keyB + (size_t)r * D);
    for (int i = threadIdx.x; i < D / 4; i += blockDim.x) {
        float4 kv = kr[i], cv = *(const float4*)(g_c2 + i * 4);
        s += kv.x * cv.x + kv.y * cv.y + kv.z * cv.z + kv.w * cv.w;
        uint2 p;
        p.x = pkbf(kv.x, kv.y);
        p.y = pkbf(kv.z, kv.w);
        ob[i] = p;
    }
    s = bsum(s, sb);
    if (threadIdx.x == 0) g_bs[r] = s;
}

// ---------- windowed query = l_att @ key, fused gates ----------
#define QT 16
__global__ __launch_bounds__(256) void k_query(const float* __restrict__ mask_src,
                                               const float* __restrict__ key,
                                               const float* __restrict__ wg,
                                               const float* __restrict__ bg,
                                               int B, int T, int S, int D) {
    __shared__ float wk[QT][64];
    __shared__ float s_c[QT], s_m[QT], s_inv[QT];
    __shared__ int s_s0[QT], s_s1[QT], sh_lo, sh_hi;
    __shared__ float red1[QT];
    int b = blockIdx.y, t0 = blockIdx.x * QT, tid = threadIdx.x;
    int lane = tid & 31;
    float step = g_steps[b];
    if (tid < QT) {
        red1[tid] = 0.f;
        int t = t0 + tid;
        if (t < T) {
            float c = step * (float)t;
            int ci = (int)lrintf(c);
            ci = min(max(ci, 0), S - 1);
            int a0 = max(0, ci - 16), a1 = min(S - 1, ci + 16);
            float mx = -INFINITY;
            for (int s = a0; s <= a1; s++) {
                float d = (float)s - c;
                mx = fmaxf(mx, -(d * d) / 0.3f - INF_ * (1.0f - mask_src[(size_t)b * S + s]));
            }
            float sum = 0.f;
            for (int s = a0; s <= a1; s++) {
                float d = (float)s - c;
                sum += __expf(-(d * d) / 0.3f - INF_ * (1.0f - mask_src[(size_t)b * S + s]) - mx);
            }
            s_c[tid] = c; s_m[tid] = mx; s_inv[tid] = 1.0f / sum;
            s_s0[tid] = a0; s_s1[tid] = a1;
        } else {
            s_c[tid] = 0.f; s_m[tid] = 0.f; s_inv[tid] = 0.f;
            s_s0[tid] = 1; s_s1[tid] = 0;
        }
    }
    __syncthreads();
    if (tid == 0) {
        int lo = s_s0[0], hi = s_s1[0];
        for (int i = 1; i < QT; i++)
            if (s_s1[i] >= s_s0[i]) { lo = min(lo, s_s0[i]); hi = max(hi, s_s1[i]); }
        sh_lo = lo; sh_hi = hi;
    }
    __syncthreads();
    int lo = sh_lo, hi = sh_hi;
    float4 acc[QT];
    #pragma unroll
    for (int r = 0; r < QT; r++) acc[r] = make_float4(0.f, 0.f, 0.f, 0.f);
    for (int c0 = lo; c0 <= hi; c0 += 64) {
        int cnt = min(64, hi - c0 + 1);
        __syncthreads();
        for (int i = tid; i < QT * 64; i += 256) {
            int tr = i >> 6, j = i & 63, s = c0 + j;
            float w = 0.f;
            if (j < cnt && s >= s_s0[tr] && s <= s_s1[tr]) {
                float d = (float)s - s_c[tr];
                w = __expf(-(d * d) / 0.3f - INF_ * (1.0f - mask_src[(size_t)b * S + s]) - s_m[tr]) * s_inv[tr];
            }
            wk[tr][j] = w;
        }
        __syncthreads();
        for (int j = 0; j < cnt; j++) {
            float4 kv = *(const float4*)(key + ((size_t)b * S + c0 + j) * D + tid * 4);
            #pragma unroll
            for (int r = 0; r < QT; r++) {
                float w = wk[r][j];
                acc[r].x = fmaf(w, kv.x, acc[r].x);
                acc[r].y = fmaf(w, kv.y, acc[r].y);
                acc[r].z = fmaf(w, kv.z, acc[r].z);
                acc[r].w = fmaf(w, kv.w, acc[r].w);
            }
        }
        __syncthreads();
    }
    float4 wgv = *(const float4*)(wg + tid * 4);
    #pragma unroll
    for (int r = 0; r < QT; r++) {
        int t = t0 + r;
        if (t < T) {
            size_t base = ((size_t)b * T + t) * D + tid * 4;
            uint2 p;
            p.x = pkbf(acc[r].x, acc[r].y);
            p.y = pkbf(acc[r].z, acc[r].w);
            *(uint2*)(g_queryB + base) = p;
        }
        float p1 = acc[r].x * wgv.x + acc[r].y * wgv.y + acc[r].z * wgv.z + acc[r].w * wgv.w;
        p1 = wsum(p1);
        if (lane == 0) atomicAdd(&red1[r], p1);
    }
    __syncthreads();
    if (tid < QT) {
        int t = t0 + tid;
        if (t < T)
            g_gates[(size_t)b * T + t] = 1.0f / (1.0f + __expf(-(red1[tid] + bg[0])));
    }
}

// ---------- mma wrappers ----------
__device__ __forceinline__ void mma_bf16(float* c, const uint32_t* a, const uint32_t* b) {
    asm volatile("mma.sync.aligned.m16n8k16.row.col.f32.bf16.bf16.f32 "
                 "{%0,%1,%2,%3},{%4,%5,%6,%7},{%8,%9},{%0,%1,%2,%3};"
                 : "+f"(c[0]), "+f"(c[1]), "+f"(c[2]), "+f"(c[3])
                 : "r"(a[0]), "r"(a[1]), "r"(a[2]), "r"(a[3]), "r"(b[0]), "r"(b[1]));
}
__device__ __forceinline__ void cpa16(uint32_t saddr, const void* g) {
    asm volatile("cp.async.cg.shared.global [%0], [%1], 16;" :: "r"(saddr), "l"(g));
}
__device__ __forceinline__ void ldsm4(uint32_t* r, uint32_t addr) {
    asm volatile("ldmatrix.sync.aligned.m8n8.x4.shared.b16 {%0,%1,%2,%3}, [%4];"
                 : "=r"(r[0]), "=r"(r[1]), "=r"(r[2]), "=r"(r[3]) : "r"(addr));
}

// ---------- bf16 NT GEMM (R10 config): 128x128 CTA, 8 warps of 64x32, 4-stage, K-chunk 32 ----------
// outmode: 0 = fp32 store, 1 = bf16 store, 2 = fp32 atomicAdd (split-K)
#define BQ 40
#define STG 4
#define SPITCH (128 * BQ)
#define GEMM_SMEM (STG * SPITCH * 2 * 2)
__global__ __launch_bounds__(256, 2) void k_bfgemm(
    const __nv_bfloat16* __restrict__ A, const __nv_bfloat16* __restrict__ B, void* __restrict__ Cout,
    int K, int lda, int ldb, int ldc,
    long long Abat, long long Bbat, long long Cbat, int outmode,
    const float* __restrict__ coladd, int colbat)
{
    extern __shared__ __align__(16) __nv_bfloat16 dsm[];
    __nv_bfloat16* Asb = dsm;
    __nv_bfloat16* Bsb = dsm + STG * SPITCH;
    int tid = threadIdx.x, lane = tid & 31, wid = tid >> 5;
    int bz = blockIdx.z;
    A += Abat * bz; B += Bbat * bz;
    int m0 = blockIdx.y * 128, n0 = blockIdx.x * 128;
    int wm = (wid & 1) * 64, wn = (wid >> 1) * 32;
    float acc[4][4][4] = {};
    int lrow = tid >> 1, lcol = (tid & 1) * 16;
    const __nv_bfloat16* agp = A + (size_t)(m0 + lrow) * lda + lcol;
    const __nv_bfloat16* bgp = B + (size_t)(n0 + lrow) * ldb + lcol;
    int nk = K >> 5;
    int soff = lrow * BQ + lcol;
    #define LTB(kt, st) do { int _k = (kt) * 32; int _o = (st) * SPITCH + soff; \
        cpa16((uint32_t)__cvta_generic_to_shared(Asb + _o), agp + _k); \
        cpa16((uint32_t)__cvta_generic_to_shared(Asb + _o + 8), agp + _k + 8); \
        cpa16((uint32_t)__cvta_generic_to_shared(Bsb + _o), bgp + _k); \
        cpa16((uint32_t)__cvta_generic_to_shared(Bsb + _o + 8), bgp + _k + 8); \
    } while (0)

    #pragma unroll
    for (int i = 0; i < STG - 1; i++) {
        if (i < nk) LTB(i, i);
        asm volatile("cp.async.commit_group;");
    }
    int arow = (lane & 15), aoffb = (lane >> 4) * 8;
    int gq = lane >> 3;
    int brow = (gq >> 1) * 8 + (lane & 7), boffb = (gq & 1) * 8;
    for (int kt = 0; kt < nk; kt++) {
        int st = kt & (STG - 1);
        asm volatile("cp.async.wait_group %0;" :: "n"(STG - 2));
        __syncthreads();
        if (kt + STG - 1 < nk) LTB(kt + STG - 1, (kt + STG - 1) & (STG - 1));
        asm volatile("cp.async.commit_group;");
        const __nv_bfloat16* Ast = Asb + st * SPITCH;
        const __nv_bfloat16* Bst = Bsb + st * SPITCH;
        #pragma unroll
        for (int kk = 0; kk < 32; kk += 16) {
            uint32_t ar[4][4], br[4][2];
            #pragma unroll
            for (int mi = 0; mi < 4; mi++)
                ldsm4(ar[mi], (uint32_t)__cvta_generic_to_shared(
                    Ast + (wm + mi * 16 + arow) * BQ + kk + aoffb));
            #pragma unroll
            for (int nj = 0; nj < 2; nj++) {
                uint32_t t4[4];
                ldsm4(t4, (uint32_t)__cvta_generic_to_shared(
                    Bst + (wn + nj * 16 + brow) * BQ + kk + boffb));
                br[nj * 2][0] = t4[0];
                br[nj * 2][1] = t4[1];
                br[nj * 2 + 1][0] = t4[2];
                br[nj * 2 + 1][1] = t4[3];
            }
            #pragma unroll
            for (int mi = 0; mi < 4; mi++)
                #pragma unroll
                for (int ni = 0; ni < 4; ni++)
                    mma_bf16(acc[mi][ni], ar[mi], br[ni]);
        }
    }
    #pragma unroll
    for (int mi = 0; mi < 4; mi++) {
        int r0 = m0 + wm + mi * 16 + (lane >> 2);
        #pragma unroll
        for (int ni = 0; ni < 4; ni++) {
            int c0 = n0 + wn + ni * 8 + (lane & 3) * 2;
            float cb0 = coladd ? coladd[(size_t)colbat * bz + c0] : 0.f;
            float cb1 = coladd ? coladd[(size_t)colbat * bz + c0 + 1] : 0.f;
            float v00 = acc[mi][ni][0] + cb0, v01 = acc[mi][ni][1] + cb1;
            float v10 = acc[mi][ni][2] + cb0, v11 = acc[mi][ni][3] + cb1;
            if (outmode == 1) {
                __nv_bfloat16* Cb = (__nv_bfloat16*)Cout + Cbat * bz;
                *(uint32_t*)(Cb + (size_t)r0 * ldc + c0) = pkbf(v00, v01);
                *(uint32_t*)(Cb + (size_t)(r0 + 8) * ldc + c0) = pkbf(v10, v11);
            } else if (outmode == 0) {
                float* Cf = (float*)Cout + Cbat * bz;
                *(float2*)(Cf + (size_t)r0 * ldc + c0) = make_float2(v00, v01);
                *(float2*)(Cf + (size_t)(r0 + 8) * ldc + c0) = make_float2(v10, v11);
            } else {
                float* Cf = (float*)Cout;
                atomicAdd(Cf + (size_t)r0 * ldc + c0, v00);
                atomicAdd(Cf + (size_t)r0 * ldc + c0 + 1, v01);
                atomicAdd(Cf + (size_t)(r0 + 8) * ldc + c0, v10);
                atomicAdd(Cf + (size_t)(r0 + 8) * ldc + c0 + 1, v11);
            }
        }
    }
}

// ---------- final: register-resident QK softmax + windowed analytic l_att ----------
// requires S == 4 * blockDim.x; processes bt = bt_base + blockIdx.x
__global__ __launch_bounds__(256) void k_final(const float* __restrict__ mask_src,
                                               float* __restrict__ out,
                                               const float* __restrict__ dots,
                                               int B, int T, int S, float invscale,
                                               int bt_base) {
    int bt = bt_base + blockIdx.x;
    int b = bt / T, t = bt - b * T;
    __shared__ float sred[32];
    __shared__ float sh_lmax, sh_linv;
    __shared__ int sh_a0, sh_a1;
    float c = g_steps[b] * (float)t;

    if (threadIdx.x < 32) {
        int ci = min(max((int)lrintf(c), 0), S - 1);
        int a0 = max(0, ci - 16), a1 = min(S - 1, ci + 16);
        float lg0 = -INFINITY, lg1 = -INFINITY;
        int s0 = a0 + (int)threadIdx.x;
        int s1 = s0 + 32;
        if (s0 <= a1) {
            float d = (float)s0 - c;
            lg0 = -(d * d) / 0.3f - INF_ * (1.0f - mask_src[(size_t)b * S + s0]);
        }
        if (s1 <= a1) {
            float d = (float)s1 - c;
            lg1 = -(d * d) / 0.3f - INF_ * (1.0f - mask_src[(size_t)b * S + s1]);
        }
        float mx = wmax(fmaxf(lg0, lg1));
        float e = 0.f;
        if (s0 <= a1) e += __expf(lg0 - mx);
        if (s1 <= a1) e += __expf(lg1 - mx);
        e = wsum(e);
        if (threadIdx.x == 0) {
            sh_lmax = mx; sh_linv = 1.0f / e; sh_a0 = a0; sh_a1 = a1;
        }
    }

    int i0 = threadIdx.x * 4;
    float4 mk = *(const float4*)(mask_src + (size_t)b * S + i0);
    float4 dv = *(const float4*)(dots + (size_t)bt * S + i0);
    float4 x;
    x.x = (dv.x - (1.0f - mk.x) * INF_) * invscale;
    x.y = (dv.y - (1.0f - mk.y) * INF_) * invscale;
    x.z = (dv.z - (1.0f - mk.z) * INF_) * invscale;
    x.w = (dv.w - (1.0f - mk.w) * INF_) * invscale;
    float qmax = fmaxf(fmaxf(x.x, x.y), fmaxf(x.z, x.w));
    qmax = bmax(qmax, sred);
    float4 e;
    e.x = __expf(x.x - qmax);
    e.y = __expf(x.y - qmax);
    e.z = __expf(x.z - qmax);
    e.w = __expf(x.w - qmax);
    float qsum = bsum(e.x + e.y + e.z + e.w, sred);
    float qinv = 1.0f / qsum;
    float g = g_gates[bt];
    float omg = 1.0f - g;
    int a0 = sh_a0, a1 = sh_a1;
    float lmax = sh_lmax, linv = sh_linv;
    float4 o;
    o.x = omg * e.x * qinv;
    o.y = omg * e.y * qinv;
    o.z = omg * e.z * qinv;
    o.w = omg * e.w * qinv;
    if (i0 + 3 >= a0 && i0 <= a1) {
        float mks[4] = {mk.x, mk.y, mk.z, mk.w};
        float* os = &o.x;
        #pragma unroll
        for (int j = 0; j < 4; j++) {
            int s = i0 + j;
            if (s >= a0 && s <= a1) {
                float d = (float)s - c;
                float lg = -(d * d) / 0.3f - INF_ * (1.0f - mks[j]);
                os[j] += g * __expf(lg - lmax) * linv;
            }
        }
    }
    *(float4*)(out + (size_t)bt * S + i0) = o;
}

// ---------- launch (multi-stream fork/join, graph-capturable) ----------
extern "C" void kernel_launch(void* const* d_in, const int* in_sizes, int n_in,
                              void* d_out, int out_size) {
    const float* key      = (const float*)d_in[0];
    const float* mask_src = (const float*)d_in[1];
    const float* mask_trg = (const float*)d_in[2];
    const float* Wq       = (const float*)d_in[3];
    const float* bq       = (const float*)d_in[4];
    const float* Wk       = (const float*)d_in[5];
    const float* bk       = (const float*)d_in[6];
    const float* wg       = (const float*)d_in[7];
    const float* bg       = (const float*)d_in[8];
    float* out = (float*)d_out;

    int D  = in_sizes[4];
    int BT = in_sizes[2];
    int S  = out_size / BT;
    int B  = in_sizes[1] / S;
    int T  = BT / B;
    int Bh = B / 2;

    float *p_Mt, *p_bs, *p_dots;
    __nv_bfloat16 *p_keyB, *p_queryB, *p_qmB, *p_MtB, *p_WqTB, *p_WkTB;
    cudaGetSymbolAddress((void**)&p_Mt,    g_Mt);
    cudaGetSymbolAddress((void**)&p_bs,    g_bs);
    cudaGetSymbolAddress((void**)&p_dots,  g_dots);
    cudaGetSymbolAddress((void**)&p_keyB,  g_keyB);
    cudaGetSymbolAddress((void**)&p_queryB, g_queryB);
    cudaGetSymbolAddress((void**)&p_qmB,   g_qmB);
    cudaGetSymbolAddress((void**)&p_MtB,   g_MtB);
    cudaGetSymbolAddress((void**)&p_WqTB,  g_WqTB);
    cudaGetSymbolAddress((void**)&p_WkTB,  g_WkTB);

    static cudaStream_t sA = nullptr, sB = nullptr;
    static cudaEvent_t e0 = nullptr, eT = nullptr, eM = nullptr, eK = nullptr,
                       eQ1 = nullptr, eD1 = nullptr, eF1 = nullptr;
    if (!sA) {
        cudaStreamCreateWithFlags(&sA, cudaStreamNonBlocking);
        cudaStreamCreateWithFlags(&sB, cudaStreamNonBlocking);
        cudaEventCreateWithFlags(&e0, cudaEventDisableTiming);
        cudaEventCreateWithFlags(&eT, cudaEventDisableTiming);
        cudaEventCreateWithFlags(&eM, cudaEventDisableTiming);
        cudaEventCreateWithFlags(&eK, cudaEventDisableTiming);
        cudaEventCreateWithFlags(&eQ1, cudaEventDisableTiming);
        cudaEventCreateWithFlags(&eD1, cudaEventDisableTiming);
        cudaEventCreateWithFlags(&eF1, cudaEventDisableTiming);
        cudaFuncSetAttribute(k_bfgemm, cudaFuncAttributeMaxDynamicSharedMemorySize, GEMM_SMEM);
    }

    long long Abat = (long long)T * D;
    long long Bbat = (long long)S * D;
    long long Cbat = (long long)T * S;
    int BTh = BT / 2;

    // main: steps (tiny)
    k_steps<<<B, 256>>>(mask_src, mask_trg, S, T);
    cudaEventRecord(e0, 0);

    // stream A (fork at e0): transp2 -> Mt split-K -> cvt -> eM
    cudaStreamWaitEvent(sA, e0, 0);
    {
        dim3 tb(32, 8);
        dim3 g(D / 32, D / 32, 2);
        k_transp2<<<g, tb, 0, sA>>>(Wq, Wk, D);
    }
    cudaEventRecord(eT, sA);
    {
        dim3 g(D / 128, D / 128, 4);
        k_bfgemm<<<g, 256, GEMM_SMEM, sA>>>(p_WkTB, p_WqTB, p_Mt, D / 4, D, D, D,
                                            D / 4, D / 4, 0, 2, nullptr, 0);
    }
    k_cvt<<<(D * D / 4 + 255) / 256, 256, 0, sA>>>(p_Mt, p_MtB, D * D / 4);
    cudaEventRecord(eM, sA);

    // stream B (fork at eT): c2 -> bskey -> eK
    cudaStreamWaitEvent(sB, eT, 0);
    k_cvecR<<<D, 128, 0, sB>>>(bq, D);
    k_bskey<<<B * S, 128, 0, sB>>>(key, D);
    cudaEventRecord(eK, sB);

    // main: windowed query + gates (overlaps streams A/B)
    {
        dim3 g((T + QT - 1) / QT, B);
        k_query<<<g, 256>>>(mask_src, key, wg, bg, B, T, S, D);
    }

    // main: qm half 1 (rows 0..BTh) — needs MtB
    cudaStreamWaitEvent(0, eM, 0);
    {
        dim3 g(D / 128, BTh / 128, 1);
        k_bfgemm<<<g, 256, GEMM_SMEM>>>(p_queryB, p_MtB, p_qmB, D, D, D, D,
                                        0, 0, 0, 1, nullptr, 0);
    }
    cudaEventRecord(eQ1, 0);

    // main: qm half 2 (rows BTh..BT)
    {
        dim3 g(D / 128, (BT - BTh) / 128, 1);
        k_bfgemm<<<g, 256, GEMM_SMEM>>>(p_queryB + (size_t)BTh * D, p_MtB,
                                        p_qmB + (size_t)BTh * D, D, D, D, D,
                                        0, 0, 0, 1, nullptr, 0);
    }

    // stream B: dots half 1 (batches 0..Bh) — after qm_h1; keyB/bs via sB program order
    cudaStreamWaitEvent(sB, eQ1, 0);
    {
        dim3 g(S / 128, T / 128, Bh);
        k_bfgemm<<<g, 256, GEMM_SMEM, sB>>>(p_qmB, p_keyB, p_dots, D, D, D, S,
                                            Abat, Bbat, Cbat, 0, p_bs, S);
    }
    // stream B: final half 1
    k_final<<<Bh * T, S / 4, 0, sB>>>(mask_src, out, p_dots, B, T, S,
                                      1.0f / sqrtf((float)D), 0);
    cudaEventRecord(eF1, sB);

    // main: dots half 2 (batches Bh..B-1) — after qm_h2 (program order) + keyB (eK)
    cudaStreamWaitEvent(0, eK, 0);
    {
        dim3 g(S / 128, T / 128, B - Bh);
        k_bfgemm<<<g, 256, GEMM_SMEM>>>(p_qmB + (size_t)Bh * Abat, p_keyB + (size_t)Bh * Bbat,
                                        p_dots + (size_t)Bh * Cbat, D, D, D, S,
                                        Abat, Bbat, Cbat, 0, p_bs + (size_t)Bh * S, S);
    }

    // main: final half 2, joined after final half 1
    cudaStreamWaitEvent(0, eF1, 0);
    k_final<<<(B - Bh) * T, S / 4>>>(mask_src, out, p_dots, B, T, S,
                                     1.0f / sqrtf((float)D), Bh * T);
}